// round 3
// baseline (speedup 1.0000x reference)
#include <cuda_runtime.h>
#include <math.h>

// Problem constants (fixed shapes from setup_inputs)
#define T_TOK 16384   // B * L
#define DMOD  512
#define LSEQ  2048
#define BATCH 8
#define HIN   128

// Scratch buffers (no cudaMalloc allowed) — 6 x 32 MB
__device__ float g_h   [(size_t)T_TOK * DMOD];  // encoder output == skip
__device__ float g_hn  [(size_t)T_TOK * DMOD];  // layernorm output / reused
__device__ float g_tmp [(size_t)T_TOK * DMOD];  // in_proj out / glu1 out / dec out
__device__ float g_bure[(size_t)T_TOK * DMOD];  // Bu real -> xs real (in-place scan)
__device__ float g_buim[(size_t)T_TOK * DMOD];  // Bu imag -> xs imag
__device__ float g_y   [(size_t)T_TOK * DMOD];  // post-gelu y

__device__ __forceinline__ float gelu_tanh(float x) {
    // jax.nn.gelu default (approximate=True)
    float x3 = x * x * x;
    return 0.5f * x * (1.f + tanhf(0.7978845608028654f * (x + 0.044715f * x3)));
}
__device__ __forceinline__ float sigmoid_f(float x) {
    return 1.f / (1.f + expf(-x));
}

// ---------------------------------------------------------------------------
// Tiled SIMT fp32 GEMM:  C[m,n] = sum_k A[m,k] * W[n,k]  (+ epilogue)
// BM=BN=128, BK=8, 256 threads, 8x8 per-thread tile.
// EPI 0: C = acc + bias[col]                       (bias may be null)
// EPI 1: C = gelu(acc(A,W) - acc(A2,W2) + e1[col]*e2[row,col])   (dual-K pass)
// EPI 2: C = e2[row,col] + e1[row,col] * sigmoid(acc + bias[col])
// All dims are multiples of tile sizes for this problem -> no bounds checks.
// ---------------------------------------------------------------------------
template<int EPI>
__global__ __launch_bounds__(256)
void gemm_kernel(const float* __restrict__ A,  const float* __restrict__ W,
                 const float* __restrict__ A2, const float* __restrict__ W2,
                 const float* __restrict__ bias,
                 const float* __restrict__ e1, const float* __restrict__ e2,
                 float* __restrict__ C, int M, int N, int K)
{
    constexpr int BM = 128, BN = 128, BK = 8, TM = 8, TN = 8;
    __shared__ float As[BK][BM];
    __shared__ float Bs[BK][BN];

    const int tid = threadIdx.x;          // 0..255
    const int tx  = tid & 15;             // output col group
    const int ty  = tid >> 4;             // output row group
    const int bm  = blockIdx.y * BM;
    const int bn  = blockIdx.x * BN;
    const int lr  = tid >> 1;             // loader row within tile (0..127)
    const int lc  = (tid & 1) * 4;        // loader col (0 or 4)

    float acc[TM][TN];
#pragma unroll
    for (int i = 0; i < TM; i++)
#pragma unroll
        for (int j = 0; j < TN; j++) acc[i][j] = 0.f;

    const int npass = (EPI == 1) ? 2 : 1;
    for (int pass = 0; pass < npass; ++pass) {
        const float* Ap = (pass ? A2 : A) + (size_t)(bm + lr) * K + lc;
        const float* Wp = (pass ? W2 : W) + (size_t)(bn + lr) * K + lc;
        const float sgn = pass ? -1.f : 1.f;   // second pass subtracts (imag part)

        for (int k0 = 0; k0 < K; k0 += BK) {
            float4 av = *(const float4*)(Ap + k0);
            float4 wv = *(const float4*)(Wp + k0);
            As[lc + 0][lr] = av.x; As[lc + 1][lr] = av.y;
            As[lc + 2][lr] = av.z; As[lc + 3][lr] = av.w;
            Bs[lc + 0][lr] = sgn * wv.x; Bs[lc + 1][lr] = sgn * wv.y;
            Bs[lc + 2][lr] = sgn * wv.z; Bs[lc + 3][lr] = sgn * wv.w;
            __syncthreads();
#pragma unroll
            for (int kk = 0; kk < BK; kk++) {
                float rm[TM], rn[TN];
#pragma unroll
                for (int i = 0; i < TM; i++) rm[i] = As[kk][ty * TM + i];
#pragma unroll
                for (int j = 0; j < TN; j++) rn[j] = Bs[kk][tx * TN + j];
#pragma unroll
                for (int i = 0; i < TM; i++)
#pragma unroll
                    for (int j = 0; j < TN; j++)
                        acc[i][j] = fmaf(rm[i], rn[j], acc[i][j]);
            }
            __syncthreads();
        }
    }

#pragma unroll
    for (int i = 0; i < TM; i++) {
        const int row = bm + ty * TM + i;
#pragma unroll
        for (int j = 0; j < TN; j++) {
            const int col = bn + tx * TN + j;
            float v = acc[i][j];
            if (EPI == 0) {
                if (bias) v += bias[col];
            } else if (EPI == 1) {
                v += e1[col] * e2[(size_t)row * DMOD + col];
                v = gelu_tanh(v);
            } else { // EPI == 2
                v = e2[(size_t)row * DMOD + col]
                  + e1[(size_t)row * DMOD + col] * sigmoid_f(v + bias[col]);
            }
            C[(size_t)row * N + col] = v;
        }
    }
}

// ---------------------------------------------------------------------------
// LayerNorm over D=512, one block (128 threads) per row, float4 vectorized.
// ---------------------------------------------------------------------------
__global__ __launch_bounds__(128)
void ln_kernel(const float* __restrict__ h, const float* __restrict__ g,
               const float* __restrict__ b, float* __restrict__ out)
{
    const int row = blockIdx.x;
    const int t = threadIdx.x;
    float4 v = ((const float4*)(h + (size_t)row * DMOD))[t];
    float s  = v.x + v.y + v.z + v.w;
    float sq = v.x * v.x + v.y * v.y + v.z * v.z + v.w * v.w;
#pragma unroll
    for (int o = 16; o > 0; o >>= 1) {
        s  += __shfl_down_sync(0xffffffff, s,  o);
        sq += __shfl_down_sync(0xffffffff, sq, o);
    }
    __shared__ float ss[4], ssq[4];
    const int w = t >> 5, l = t & 31;
    if (l == 0) { ss[w] = s; ssq[w] = sq; }
    __syncthreads();
    if (t == 0) {
        float S  = ss[0]  + ss[1]  + ss[2]  + ss[3];
        float SQ = ssq[0] + ssq[1] + ssq[2] + ssq[3];
        float mu  = S * (1.f / DMOD);
        float var = SQ * (1.f / DMOD) - mu * mu;
        ss[0]  = mu;
        ssq[0] = rsqrtf(var + 1e-5f);
    }
    __syncthreads();
    const float mu = ss[0], rstd = ssq[0];
    float4 gv = ((const float4*)g)[t];
    float4 bv = ((const float4*)b)[t];
    float4 o4;
    o4.x = (v.x - mu) * rstd * gv.x + bv.x;
    o4.y = (v.y - mu) * rstd * gv.y + bv.y;
    o4.z = (v.z - mu) * rstd * gv.z + bv.z;
    o4.w = (v.w - mu) * rstd * gv.w + bv.w;
    ((float4*)(out + (size_t)row * DMOD))[t] = o4;
}

// ---------------------------------------------------------------------------
// LinOSS-IM recurrence. Transition matrix M is time-invariant per channel, so
// the associative scan reduces to a plain sequential recurrence:
//   [z;x]_t = M [z;x]_{t-1} + [c1;c2]*Bu_t   (complex Bu, real M)
// One thread per (batch, channel) chain: 4096 threads, 2048 steps.
// Coalesced: consecutive threads = consecutive channels at the same timestep.
// In-place: bu_{re,im} is overwritten with xs_{re,im}.
// ---------------------------------------------------------------------------
__global__ __launch_bounds__(256)
void scan_kernel(float* __restrict__ bu_re, float* __restrict__ bu_im,
                 const float* __restrict__ A_diag,
                 const float* __restrict__ log_steps)
{
    const int tid = blockIdx.x * blockDim.x + threadIdx.x;  // 0..4095
    const int n = tid & (DMOD - 1);
    const int b = tid >> 9;

    const float Ad  = fmaxf(A_diag[n], 0.f);
    const float dt  = 1.f / (1.f + expf(-log_steps[n]));
    const float S   = 1.f / (1.f + dt * dt * Ad);
    const float m11 = 1.f - dt * dt * Ad * S;
    const float m12 = -dt * Ad * S;
    const float m21 = dt * S;
    const float m22 = S;
    const float c1  = m11 * dt;
    const float c2  = m21 * dt;

    size_t idx = (size_t)b * LSEQ * DMOD + n;
    float zr = 0.f, zi = 0.f, xr = 0.f, xi = 0.f;
    for (int t = 0; t < LSEQ; t++, idx += DMOD) {
        const float br_ = bu_re[idx];
        const float bi_ = bu_im[idx];
        const float nzr = fmaf(m11, zr, fmaf(m12, xr, c1 * br_));
        const float nzi = fmaf(m11, zi, fmaf(m12, xi, c1 * bi_));
        const float nxr = fmaf(m21, zr, fmaf(m22, xr, c2 * br_));
        const float nxi = fmaf(m21, zi, fmaf(m22, xi, c2 * bi_));
        zr = nzr; zi = nzi; xr = nxr; xi = nxi;
        bu_re[idx] = xr;
        bu_im[idx] = xi;
    }
}

// ---------------------------------------------------------------------------
extern "C" void kernel_launch(void* const* d_in, const int* in_sizes, int n_in,
                              void* d_out, int out_size)
{
    const float* x        = (const float*)d_in[0];
    const float* W_in     = (const float*)d_in[1];
    const float* b_in     = (const float*)d_in[2];
    const float* W_enc    = (const float*)d_in[3];
    const float* b_enc    = (const float*)d_in[4];
    const float* ln_g     = (const float*)d_in[5];
    const float* ln_b     = (const float*)d_in[6];
    const float* A_diag   = (const float*)d_in[7];
    const float* log_steps= (const float*)d_in[8];
    const float* B_re     = (const float*)d_in[9];
    const float* B_im     = (const float*)d_in[10];
    const float* C_re     = (const float*)d_in[11];
    const float* C_im     = (const float*)d_in[12];
    const float* Dv       = (const float*)d_in[13];
    const float* glu_w1   = (const float*)d_in[14];
    const float* glu_b1   = (const float*)d_in[15];
    const float* glu_w2   = (const float*)d_in[16];
    const float* glu_b2   = (const float*)d_in[17];
    const float* W_dec    = (const float*)d_in[18];
    const float* b_dec    = (const float*)d_in[19];
    const float* W_out    = (const float*)d_in[20];
    const float* b_out    = (const float*)d_in[21];
    float* out = (float*)d_out;

    float *h, *hn, *tmp, *bre, *bim, *y;
    cudaGetSymbolAddress((void**)&h,   g_h);
    cudaGetSymbolAddress((void**)&hn,  g_hn);
    cudaGetSymbolAddress((void**)&tmp, g_tmp);
    cudaGetSymbolAddress((void**)&bre, g_bure);
    cudaGetSymbolAddress((void**)&bim, g_buim);
    cudaGetSymbolAddress((void**)&y,   g_y);

    dim3 blk(256);
    dim3 g512(DMOD / 128, T_TOK / 128);   // N=512 GEMMs
    dim3 g128(HIN  / 128, T_TOK / 128);   // N=128 GEMM (out_proj)

    // 1) h0 = x @ W_in^T + b_in                       (K=128)
    gemm_kernel<0><<<g512, blk>>>(x, W_in, nullptr, nullptr, b_in,
                                  nullptr, nullptr, tmp, T_TOK, DMOD, HIN);
    // 2) h = h0 @ W_enc^T + b_enc  (== skip)
    gemm_kernel<0><<<g512, blk>>>(tmp, W_enc, nullptr, nullptr, b_enc,
                                  nullptr, nullptr, h, T_TOK, DMOD, DMOD);
    // 3) hn = LayerNorm(h)
    ln_kernel<<<T_TOK, 128>>>(h, ln_g, ln_b, hn);
    // 4) Bu_re = hn @ B_re^T ; Bu_im = hn @ B_im^T
    gemm_kernel<0><<<g512, blk>>>(hn, B_re, nullptr, nullptr, nullptr,
                                  nullptr, nullptr, bre, T_TOK, DMOD, DMOD);
    gemm_kernel<0><<<g512, blk>>>(hn, B_im, nullptr, nullptr, nullptr,
                                  nullptr, nullptr, bim, T_TOK, DMOD, DMOD);
    // 5) xs = linoss_scan_im(A, dt, Bu)   (in place)
    scan_kernel<<<16, 256>>>(bre, bim, A_diag, log_steps);
    // 6) y = gelu( xs_re @ C_re^T - xs_im @ C_im^T + D*hn )
    gemm_kernel<1><<<g512, blk>>>(bre, C_re, bim, C_im, nullptr,
                                  Dv, hn, y, T_TOK, DMOD, DMOD);
    // 7) g1 = y @ glu_w1^T + glu_b1
    gemm_kernel<0><<<g512, blk>>>(y, glu_w1, nullptr, nullptr, glu_b1,
                                  nullptr, nullptr, tmp, T_TOK, DMOD, DMOD);
    // 8) h2 = skip + g1 * sigmoid(y @ glu_w2^T + glu_b2)
    gemm_kernel<2><<<g512, blk>>>(y, glu_w2, nullptr, nullptr, glu_b2,
                                  tmp, h, hn, T_TOK, DMOD, DMOD);
    // 9) dec = h2 @ W_dec^T + b_dec
    gemm_kernel<0><<<g512, blk>>>(hn, W_dec, nullptr, nullptr, b_dec,
                                  nullptr, nullptr, tmp, T_TOK, DMOD, DMOD);
    // 10) out = dec @ W_out^T + b_out                 (N=128)
    gemm_kernel<0><<<g128, blk>>>(tmp, W_out, nullptr, nullptr, b_out,
                                  nullptr, nullptr, out, T_TOK, HIN, DMOD);
}

// round 7
// speedup vs baseline: 1.0119x; 1.0119x over previous
#include <cuda_runtime.h>
#include <math.h>

// Problem constants (fixed shapes from setup_inputs)
#define T_TOK 16384   // B * L
#define DMOD  512
#define LSEQ  2048
#define BATCH 8
#define HIN   128

// Scratch buffers (no cudaMalloc allowed) — 6 x 32 MB
__device__ float g_h   [(size_t)T_TOK * DMOD];  // encoder output == skip
__device__ float g_hn  [(size_t)T_TOK * DMOD];  // layernorm output / reused
__device__ float g_tmp [(size_t)T_TOK * DMOD];  // in_proj out / glu1 out / dec out
__device__ float g_bure[(size_t)T_TOK * DMOD];  // Bu real -> xs real (in-place scan)
__device__ float g_buim[(size_t)T_TOK * DMOD];  // Bu imag -> xs imag
__device__ float g_y   [(size_t)T_TOK * DMOD];  // post-gelu y

__device__ __forceinline__ float gelu_tanh(float x) {
    // jax.nn.gelu default (approximate=True)
    float x3 = x * x * x;
    return 0.5f * x * (1.f + tanhf(0.7978845608028654f * (x + 0.044715f * x3)));
}
__device__ __forceinline__ float sigmoid_f(float x) {
    return 1.f / (1.f + expf(-x));
}

// ---------------------------------------------------------------------------
// Tiled SIMT fp32 GEMM:  C[m,n] = sum_k A[m,k] * W[n,k]  (+ epilogue)
// BM=BN=128, BK=8, 256 threads, 8x8 per-thread tile.
// EPI 0: C = acc + bias[col]                       (bias may be null)
// EPI 1: C = gelu(acc(A,W) - acc(A2,W2) + e1[col]*e2[row,col])   (dual-K pass)
// EPI 2: C = e2[row,col] + e1[row,col] * sigmoid(acc + bias[col])
// All dims are multiples of tile sizes for this problem -> no bounds checks.
// ---------------------------------------------------------------------------
template<int EPI>
__global__ __launch_bounds__(256)
void gemm_kernel(const float* __restrict__ A,  const float* __restrict__ W,
                 const float* __restrict__ A2, const float* __restrict__ W2,
                 const float* __restrict__ bias,
                 const float* __restrict__ e1, const float* __restrict__ e2,
                 float* __restrict__ C, int M, int N, int K)
{
    constexpr int BM = 128, BN = 128, BK = 8, TM = 8, TN = 8;
    __shared__ float As[BK][BM];
    __shared__ float Bs[BK][BN];

    const int tid = threadIdx.x;          // 0..255
    const int tx  = tid & 15;             // output col group
    const int ty  = tid >> 4;             // output row group
    const int bm  = blockIdx.y * BM;
    const int bn  = blockIdx.x * BN;
    const int lr  = tid >> 1;             // loader row within tile (0..127)
    const int lc  = (tid & 1) * 4;        // loader col (0 or 4)

    float acc[TM][TN];
#pragma unroll
    for (int i = 0; i < TM; i++)
#pragma unroll
        for (int j = 0; j < TN; j++) acc[i][j] = 0.f;

    const int npass = (EPI == 1) ? 2 : 1;
    for (int pass = 0; pass < npass; ++pass) {
        const float* Ap = (pass ? A2 : A) + (size_t)(bm + lr) * K + lc;
        const float* Wp = (pass ? W2 : W) + (size_t)(bn + lr) * K + lc;
        const float sgn = pass ? -1.f : 1.f;   // second pass subtracts (imag part)

        for (int k0 = 0; k0 < K; k0 += BK) {
            float4 av = *(const float4*)(Ap + k0);
            float4 wv = *(const float4*)(Wp + k0);
            As[lc + 0][lr] = av.x; As[lc + 1][lr] = av.y;
            As[lc + 2][lr] = av.z; As[lc + 3][lr] = av.w;
            Bs[lc + 0][lr] = sgn * wv.x; Bs[lc + 1][lr] = sgn * wv.y;
            Bs[lc + 2][lr] = sgn * wv.z; Bs[lc + 3][lr] = sgn * wv.w;
            __syncthreads();
#pragma unroll
            for (int kk = 0; kk < BK; kk++) {
                float rm[TM], rn[TN];
#pragma unroll
                for (int i = 0; i < TM; i++) rm[i] = As[kk][ty * TM + i];
#pragma unroll
                for (int j = 0; j < TN; j++) rn[j] = Bs[kk][tx * TN + j];
#pragma unroll
                for (int i = 0; i < TM; i++)
#pragma unroll
                    for (int j = 0; j < TN; j++)
                        acc[i][j] = fmaf(rm[i], rn[j], acc[i][j]);
            }
            __syncthreads();
        }
    }

#pragma unroll
    for (int i = 0; i < TM; i++) {
        const int row = bm + ty * TM + i;
#pragma unroll
        for (int j = 0; j < TN; j++) {
            const int col = bn + tx * TN + j;
            float v = acc[i][j];
            if (EPI == 0) {
                if (bias) v += bias[col];
            } else if (EPI == 1) {
                v += e1[col] * e2[(size_t)row * DMOD + col];
                v = gelu_tanh(v);
            } else { // EPI == 2
                v = e2[(size_t)row * DMOD + col]
                  + e1[(size_t)row * DMOD + col] * sigmoid_f(v + bias[col]);
            }
            C[(size_t)row * N + col] = v;
        }
    }
}

// ---------------------------------------------------------------------------
// LayerNorm over D=512, one block (128 threads) per row, float4 vectorized.
// ---------------------------------------------------------------------------
__global__ __launch_bounds__(128)
void ln_kernel(const float* __restrict__ h, const float* __restrict__ g,
               const float* __restrict__ b, float* __restrict__ out)
{
    const int row = blockIdx.x;
    const int t = threadIdx.x;
    float4 v = ((const float4*)(h + (size_t)row * DMOD))[t];
    float s  = v.x + v.y + v.z + v.w;
    float sq = v.x * v.x + v.y * v.y + v.z * v.z + v.w * v.w;
#pragma unroll
    for (int o = 16; o > 0; o >>= 1) {
        s  += __shfl_down_sync(0xffffffff, s,  o);
        sq += __shfl_down_sync(0xffffffff, sq, o);
    }
    __shared__ float ss[4], ssq[4];
    const int w = t >> 5, l = t & 31;
    if (l == 0) { ss[w] = s; ssq[w] = sq; }
    __syncthreads();
    if (t == 0) {
        float S  = ss[0]  + ss[1]  + ss[2]  + ss[3];
        float SQ = ssq[0] + ssq[1] + ssq[2] + ssq[3];
        float mu  = S * (1.f / DMOD);
        float var = SQ * (1.f / DMOD) - mu * mu;
        ss[0]  = mu;
        ssq[0] = rsqrtf(var + 1e-5f);
    }
    __syncthreads();
    const float mu = ss[0], rstd = ssq[0];
    float4 gv = ((const float4*)g)[t];
    float4 bv = ((const float4*)b)[t];
    float4 o4;
    o4.x = (v.x - mu) * rstd * gv.x + bv.x;
    o4.y = (v.y - mu) * rstd * gv.y + bv.y;
    o4.z = (v.z - mu) * rstd * gv.z + bv.z;
    o4.w = (v.w - mu) * rstd * gv.w + bv.w;
    ((float4*)(out + (size_t)row * DMOD))[t] = o4;
}

// ---------------------------------------------------------------------------
// LinOSS-IM recurrence. Transition matrix M is time-invariant per channel, so
// the associative scan reduces to a plain sequential recurrence:
//   [z;x]_t = M [z;x]_{t-1} + [c1;c2]*Bu_t   (complex Bu, real M)
// One thread per (batch, channel) chain: 4096 threads, 2048 steps.
// Coalesced: consecutive threads = consecutive channels at the same timestep.
// In-place: bu_{re,im} is overwritten with xs_{re,im}.
// ---------------------------------------------------------------------------
__global__ __launch_bounds__(256)
void scan_kernel(float* __restrict__ bu_re, float* __restrict__ bu_im,
                 const float* __restrict__ A_diag,
                 const float* __restrict__ log_steps)
{
    const int tid = blockIdx.x * blockDim.x + threadIdx.x;  // 0..4095
    const int n = tid & (DMOD - 1);
    const int b = tid >> 9;

    const float Ad  = fmaxf(A_diag[n], 0.f);
    const float dt  = 1.f / (1.f + expf(-log_steps[n]));
    const float S   = 1.f / (1.f + dt * dt * Ad);
    const float m11 = 1.f - dt * dt * Ad * S;
    const float m12 = -dt * Ad * S;
    const float m21 = dt * S;
    const float m22 = S;
    const float c1  = m11 * dt;
    const float c2  = m21 * dt;

    size_t idx = (size_t)b * LSEQ * DMOD + n;
    float zr = 0.f, zi = 0.f, xr = 0.f, xi = 0.f;
    for (int t = 0; t < LSEQ; t++, idx += DMOD) {
        const float br_ = bu_re[idx];
        const float bi_ = bu_im[idx];
        const float nzr = fmaf(m11, zr, fmaf(m12, xr, c1 * br_));
        const float nzi = fmaf(m11, zi, fmaf(m12, xi, c1 * bi_));
        const float nxr = fmaf(m21, zr, fmaf(m22, xr, c2 * br_));
        const float nxi = fmaf(m21, zi, fmaf(m22, xi, c2 * bi_));
        zr = nzr; zi = nzi; xr = nxr; xi = nxi;
        bu_re[idx] = xr;
        bu_im[idx] = xi;
    }
}

// ---------------------------------------------------------------------------
extern "C" void kernel_launch(void* const* d_in, const int* in_sizes, int n_in,
                              void* d_out, int out_size)
{
    const float* x        = (const float*)d_in[0];
    const float* W_in     = (const float*)d_in[1];
    const float* b_in     = (const float*)d_in[2];
    const float* W_enc    = (const float*)d_in[3];
    const float* b_enc    = (const float*)d_in[4];
    const float* ln_g     = (const float*)d_in[5];
    const float* ln_b     = (const float*)d_in[6];
    const float* A_diag   = (const float*)d_in[7];
    const float* log_steps= (const float*)d_in[8];
    const float* B_re     = (const float*)d_in[9];
    const float* B_im     = (const float*)d_in[10];
    const float* C_re     = (const float*)d_in[11];
    const float* C_im     = (const float*)d_in[12];
    const float* Dv       = (const float*)d_in[13];
    const float* glu_w1   = (const float*)d_in[14];
    const float* glu_b1   = (const float*)d_in[15];
    const float* glu_w2   = (const float*)d_in[16];
    const float* glu_b2   = (const float*)d_in[17];
    const float* W_dec    = (const float*)d_in[18];
    const float* b_dec    = (const float*)d_in[19];
    const float* W_out    = (const float*)d_in[20];
    const float* b_out    = (const float*)d_in[21];
    float* out = (float*)d_out;

    float *h, *hn, *tmp, *bre, *bim, *y;
    cudaGetSymbolAddress((void**)&h,   g_h);
    cudaGetSymbolAddress((void**)&hn,  g_hn);
    cudaGetSymbolAddress((void**)&tmp, g_tmp);
    cudaGetSymbolAddress((void**)&bre, g_bure);
    cudaGetSymbolAddress((void**)&bim, g_buim);
    cudaGetSymbolAddress((void**)&y,   g_y);

    dim3 blk(256);
    dim3 g512(DMOD / 128, T_TOK / 128);   // N=512 GEMMs
    dim3 g128(HIN  / 128, T_TOK / 128);   // N=128 GEMM (out_proj)

    // 1) h0 = x @ W_in^T + b_in                       (K=128)
    gemm_kernel<0><<<g512, blk>>>(x, W_in, nullptr, nullptr, b_in,
                                  nullptr, nullptr, tmp, T_TOK, DMOD, HIN);
    // 2) h = h0 @ W_enc^T + b_enc  (== skip)
    gemm_kernel<0><<<g512, blk>>>(tmp, W_enc, nullptr, nullptr, b_enc,
                                  nullptr, nullptr, h, T_TOK, DMOD, DMOD);
    // 3) hn = LayerNorm(h)
    ln_kernel<<<T_TOK, 128>>>(h, ln_g, ln_b, hn);
    // 4) Bu_re = hn @ B_re^T ; Bu_im = hn @ B_im^T
    gemm_kernel<0><<<g512, blk>>>(hn, B_re, nullptr, nullptr, nullptr,
                                  nullptr, nullptr, bre, T_TOK, DMOD, DMOD);
    gemm_kernel<0><<<g512, blk>>>(hn, B_im, nullptr, nullptr, nullptr,
                                  nullptr, nullptr, bim, T_TOK, DMOD, DMOD);
    // 5) xs = linoss_scan_im(A, dt, Bu)   (in place)
    scan_kernel<<<16, 256>>>(bre, bim, A_diag, log_steps);
    // 6) y = gelu( xs_re @ C_re^T - xs_im @ C_im^T + D*hn )
    gemm_kernel<1><<<g512, blk>>>(bre, C_re, bim, C_im, nullptr,
                                  Dv, hn, y, T_TOK, DMOD, DMOD);
    // 7) g1 = y @ glu_w1^T + glu_b1
    gemm_kernel<0><<<g512, blk>>>(y, glu_w1, nullptr, nullptr, glu_b1,
                                  nullptr, nullptr, tmp, T_TOK, DMOD, DMOD);
    // 8) h2 = skip + g1 * sigmoid(y @ glu_w2^T + glu_b2)
    gemm_kernel<2><<<g512, blk>>>(y, glu_w2, nullptr, nullptr, glu_b2,
                                  tmp, h, hn, T_TOK, DMOD, DMOD);
    // 9) dec = h2 @ W_dec^T + b_dec
    gemm_kernel<0><<<g512, blk>>>(hn, W_dec, nullptr, nullptr, b_dec,
                                  nullptr, nullptr, tmp, T_TOK, DMOD, DMOD);
    // 10) out = dec @ W_out^T + b_out                 (N=128)
    gemm_kernel<0><<<g128, blk>>>(tmp, W_out, nullptr, nullptr, b_out,
                                  nullptr, nullptr, out, T_TOK, HIN, DMOD);
}

// round 9
// speedup vs baseline: 3.3034x; 3.2645x over previous
#include <cuda_runtime.h>
#include <cuda_bf16.h>
#include <math.h>
#include <stdint.h>

#define T_TOK 16384
#define DMOD  512
#define LSEQ  2048
#define BATCH 8
#define HIN   128
#define GCH   16
#define CLEN  128          // LSEQ / GCH
#define ST_PLANE (BATCH*GCH*DMOD)

// ---------------- scratch (__device__ globals; no cudaMalloc) ----------------
__device__ float g_H  [(size_t)T_TOK*DMOD];   // encoder out == skip (fp32)
__device__ float g_HN [(size_t)T_TOK*DMOD];   // layernorm out (fp32)
__device__ float g_BRE[(size_t)T_TOK*DMOD];   // Bu real (fp32)
__device__ float g_BIM[(size_t)T_TOK*DMOD];   // Bu imag (fp32)
__device__ float g_G1 [(size_t)T_TOK*DMOD];   // glu1 out (fp32)
__device__ float g_ST [4*ST_PLANE];           // scan chunk states
__device__ float g_IN [4*ST_PLANE];           // scan chunk init states

// bf16 hi/lo activation pairs
__device__ __nv_bfloat16 g_XH [(size_t)T_TOK*HIN],  g_XL [(size_t)T_TOK*HIN];
__device__ __nv_bfloat16 g_T1H[(size_t)T_TOK*DMOD], g_T1L[(size_t)T_TOK*DMOD];
__device__ __nv_bfloat16 g_HNH[(size_t)T_TOK*DMOD], g_HNL[(size_t)T_TOK*DMOD];
__device__ __nv_bfloat16 g_XRH[(size_t)T_TOK*DMOD], g_XRL[(size_t)T_TOK*DMOD];
__device__ __nv_bfloat16 g_XIH[(size_t)T_TOK*DMOD], g_XIL[(size_t)T_TOK*DMOD];
__device__ __nv_bfloat16 g_YH [(size_t)T_TOK*DMOD], g_YL [(size_t)T_TOK*DMOD];
__device__ __nv_bfloat16 g_H2H[(size_t)T_TOK*DMOD], g_H2L[(size_t)T_TOK*DMOD];
__device__ __nv_bfloat16 g_DH [(size_t)T_TOK*DMOD], g_DL [(size_t)T_TOK*DMOD];

// bf16 hi/lo weight pairs
__device__ __nv_bfloat16 w_INH [DMOD*HIN],  w_INL [DMOD*HIN];
__device__ __nv_bfloat16 w_ENCH[DMOD*DMOD], w_ENCL[DMOD*DMOD];
__device__ __nv_bfloat16 w_BRH [DMOD*DMOD], w_BRL [DMOD*DMOD];
__device__ __nv_bfloat16 w_BIH [DMOD*DMOD], w_BIL [DMOD*DMOD];
__device__ __nv_bfloat16 w_CRH [DMOD*DMOD], w_CRL [DMOD*DMOD];
__device__ __nv_bfloat16 w_CIH [DMOD*DMOD], w_CIL [DMOD*DMOD]; // pre-negated
__device__ __nv_bfloat16 w_G1H [DMOD*DMOD], w_G1L [DMOD*DMOD];
__device__ __nv_bfloat16 w_G2H [DMOD*DMOD], w_G2L [DMOD*DMOD];
__device__ __nv_bfloat16 w_DEH [DMOD*DMOD], w_DEL [DMOD*DMOD];
__device__ __nv_bfloat16 w_OUH [HIN*DMOD],  w_OUL [HIN*DMOD];

// ---------------- helpers ----------------
__device__ __forceinline__ float gelu_tanh(float x) {
    float x3 = x * x * x;
    return 0.5f * x * (1.f + tanhf(0.7978845608028654f * (x + 0.044715f * x3)));
}
__device__ __forceinline__ float sigmoid_f(float x) { return 1.f / (1.f + expf(-x)); }

__device__ __forceinline__ void split_pair(float a, float b, uint32_t& h, uint32_t& l) {
    __nv_bfloat16 ha = __float2bfloat16(a), hb = __float2bfloat16(b);
    __nv_bfloat162 th; th.x = ha; th.y = hb;
    __nv_bfloat162 tl;
    tl.x = __float2bfloat16(a - __bfloat162float(ha));
    tl.y = __float2bfloat16(b - __bfloat162float(hb));
    h = *reinterpret_cast<uint32_t*>(&th);
    l = *reinterpret_cast<uint32_t*>(&tl);
}
__device__ __forceinline__ uint32_t smem_u32(const void* p) {
    uint32_t a;
    asm("{ .reg .u64 t; cvta.to.shared.u64 t, %1; cvt.u32.u64 %0, t; }" : "=r"(a) : "l"(p));
    return a;
}

// ldmatrix: 4x 8x8 b16 matrices
#define LDSM4(r, addr)                                                          \
    asm volatile("ldmatrix.sync.aligned.m8n8.x4.shared.b16 {%0,%1,%2,%3}, [%4];"\
        : "=r"((r)[0]), "=r"((r)[1]), "=r"((r)[2]), "=r"((r)[3]) : "r"(addr))

// mma m16n8k16 bf16 -> fp32 accumulate in place
#define MMA16816(d, a, b)                                                       \
    asm volatile("mma.sync.aligned.m16n8k16.row.col.f32.bf16.bf16.f32 "        \
        "{%0,%1,%2,%3}, {%4,%5,%6,%7}, {%8,%9}, {%0,%1,%2,%3};"                \
        : "+f"((d)[0]), "+f"((d)[1]), "+f"((d)[2]), "+f"((d)[3])               \
        : "r"((a)[0]), "r"((a)[1]), "r"((a)[2]), "r"((a)[3]),                  \
          "r"((b)[0]), "r"((b)[1]))

// ---------------- fp32 -> (hi, lo) bf16 ----------------
__global__ __launch_bounds__(256)
void conv_split(const float* __restrict__ src, __nv_bfloat16* __restrict__ dh,
                __nv_bfloat16* __restrict__ dl, int n4, float sgn)
{
    int i = blockIdx.x * blockDim.x + threadIdx.x;
    if (i >= n4) return;
    float4 v = ((const float4*)src)[i];
    uint2 uh, ul;
    split_pair(sgn * v.x, sgn * v.y, uh.x, ul.x);
    split_pair(sgn * v.z, sgn * v.w, uh.y, ul.y);
    ((uint2*)dh)[i] = uh;
    ((uint2*)dl)[i] = ul;
}

// ---------------- split-bf16 GEMM on the tensor pipe (mma.sync) ----------------
// C[m,n] = sum_k A[m,k]*W[n,k]; A=AH+AL, W=BH+BL (bf16 splits); fp32 accum.
// 3-term: ah*bh + al*bh + ah*bl  (drops al*bl ~ 2^-16 relative).
// CTA tile 128x128, K-chunk 32. 8 warps: warp (wid&3) -> 32 rows, (wid>>2) -> 64 cols.
// EPI 0: v = acc (+bias[col])
// EPI 1: dual accumulate (A,W)+(A2,W2); v = gelu(acc + e1[col]*e2[row,col])
// EPI 2: v = e2[row,col] + e1[row,col]*sigmoid(acc + bias[col])
// SMEM: 4 tiles of 128 rows x 80B (32 bf16 data + pad) at 0/10240/20480/30720;
// epilogue reuses smem as 128x132 fp32 staging (67584 B total).
#define TILE_STRIDE 80
#define TILE_BYTES  10240
#define GEMM_SMEM   67584

template<int EPI>
__global__ __launch_bounds__(256, 2)
void mma_gemm(const __nv_bfloat16* __restrict__ AH, const __nv_bfloat16* __restrict__ AL,
              const __nv_bfloat16* __restrict__ BH, const __nv_bfloat16* __restrict__ BL,
              const __nv_bfloat16* __restrict__ A2H, const __nv_bfloat16* __restrict__ A2L,
              const __nv_bfloat16* __restrict__ B2H, const __nv_bfloat16* __restrict__ B2L,
              const float* __restrict__ bias,
              const float* __restrict__ e1, const float* __restrict__ e2,
              float* __restrict__ outF,
              __nv_bfloat16* __restrict__ outH, __nv_bfloat16* __restrict__ outL,
              int N, int K)
{
    extern __shared__ char smem[];
    const uint32_t sb = smem_u32(smem);
    const int tid = threadIdx.x, wid = tid >> 5, lane = tid & 31;
    const int bm = blockIdx.y * 128, bn = blockIdx.x * 128;
    const int wm = (wid & 3) * 32, wn = (wid >> 2) * 64;

    float acc[2][8][4];
#pragma unroll
    for (int i = 0; i < 2; i++)
#pragma unroll
        for (int j = 0; j < 8; j++)
#pragma unroll
            for (int k = 0; k < 4; k++) acc[i][j][k] = 0.f;

    // ldmatrix lane address components
    const int a_row  = lane & 15;            // + (lane>>4) selects k-half
    const int a_byte = (lane >> 4) * 16;
    const int bg     = lane >> 3;            // 4 groups of 8
    const int b_row  = (bg >> 1) * 8 + (lane & 7);
    const int b_byte = (bg & 1) * 16;

    const int kchunks = K / 32;
    const int nchunks = (EPI == 1 ? 2 : 1) * kchunks;

    for (int c = 0; c < nchunks; ++c) {
        const __nv_bfloat16 *ah, *al, *bh, *bl; int k0;
        if (EPI == 1 && c >= kchunks) {
            ah = A2H; al = A2L; bh = B2H; bl = B2L; k0 = (c - kchunks) * 32;
        } else {
            ah = AH; al = AL; bh = BH; bl = BL; k0 = c * 32;
        }
        __syncthreads();   // previous chunk's ldmatrix reads done
        {
            const __nv_bfloat16* srcs[4] = {ah, al, bh, bl};
            const int br4[4] = {bm, bm, bn, bn};
#pragma unroll
            for (int sub = 0; sub < 4; ++sub) {
#pragma unroll
                for (int it = 0; it < 2; ++it) {
                    int q = tid + it * 256;          // 512 16B quads per tile
                    int row = q >> 2, c16 = q & 3;
                    uint4 v = *(const uint4*)(srcs[sub] + (size_t)(br4[sub] + row) * K + k0 + c16 * 8);
                    *(uint4*)(smem + sub * TILE_BYTES + row * TILE_STRIDE + c16 * 16) = v;
                }
            }
        }
        __syncthreads();

#pragma unroll
        for (int ks = 0; ks < 2; ++ks) {             // two k16 steps per chunk
            uint32_t af[2][4], bf[8][2], xf[2][4];
            // A-hi fragments
#pragma unroll
            for (int mt = 0; mt < 2; ++mt) {
                uint32_t ad = sb + (wm + mt * 16 + a_row) * TILE_STRIDE + ks * 32 + a_byte;
                LDSM4(af[mt], ad);
            }
            // B-hi fragments (each ldsm4 covers 2 n-tiles)
#pragma unroll
            for (int j = 0; j < 4; ++j) {
                uint32_t ad = sb + 2 * TILE_BYTES + (wn + j * 16 + b_row) * TILE_STRIDE + ks * 32 + b_byte;
                uint32_t r[4]; LDSM4(r, ad);
                bf[2*j][0] = r[0]; bf[2*j][1] = r[1];
                bf[2*j+1][0] = r[2]; bf[2*j+1][1] = r[3];
            }
#pragma unroll
            for (int mt = 0; mt < 2; ++mt)
#pragma unroll
                for (int nt = 0; nt < 8; ++nt) MMA16816(acc[mt][nt], af[mt], bf[nt]);
            // A-lo fragments: al*bh
#pragma unroll
            for (int mt = 0; mt < 2; ++mt) {
                uint32_t ad = sb + TILE_BYTES + (wm + mt * 16 + a_row) * TILE_STRIDE + ks * 32 + a_byte;
                LDSM4(xf[mt], ad);
            }
#pragma unroll
            for (int mt = 0; mt < 2; ++mt)
#pragma unroll
                for (int nt = 0; nt < 8; ++nt) MMA16816(acc[mt][nt], xf[mt], bf[nt]);
            // B-lo fragments (overwrite bf): ah*bl
#pragma unroll
            for (int j = 0; j < 4; ++j) {
                uint32_t ad = sb + 3 * TILE_BYTES + (wn + j * 16 + b_row) * TILE_STRIDE + ks * 32 + b_byte;
                uint32_t r[4]; LDSM4(r, ad);
                bf[2*j][0] = r[0]; bf[2*j][1] = r[1];
                bf[2*j+1][0] = r[2]; bf[2*j+1][1] = r[3];
            }
#pragma unroll
            for (int mt = 0; mt < 2; ++mt)
#pragma unroll
                for (int nt = 0; nt < 8; ++nt) MMA16816(acc[mt][nt], af[mt], bf[nt]);
        }
    }

    // ---- stage accumulators to SMEM (128 x 132 fp32), then fused epilogue ----
    __syncthreads();
    float* stg = (float*)smem;
#pragma unroll
    for (int mt = 0; mt < 2; ++mt)
#pragma unroll
        for (int nt = 0; nt < 8; ++nt)
#pragma unroll
            for (int h = 0; h < 2; ++h) {
                int r  = wm + mt * 16 + (lane >> 2) + h * 8;
                int cc = wn + nt * 8 + (lane & 3) * 2;
                *(float2*)(stg + r * 132 + cc) =
                    make_float2(acc[mt][nt][h * 2], acc[mt][nt][h * 2 + 1]);
            }
    __syncthreads();

    for (int i = tid; i < 128 * 32; i += 256) {
        int r = i >> 5, c4 = (i & 31) * 4;
        float4 v = *(const float4*)(stg + r * 132 + c4);
        const int row = bm + r, col = bn + c4;
        if (EPI == 0) {
            if (bias) {
                float4 bb = *(const float4*)(bias + col);
                v.x += bb.x; v.y += bb.y; v.z += bb.z; v.w += bb.w;
            }
        } else if (EPI == 1) {
            float4 dd = *(const float4*)(e1 + col);
            float4 hh = *(const float4*)(e2 + (size_t)row * DMOD + col);
            v.x = gelu_tanh(v.x + dd.x * hh.x);
            v.y = gelu_tanh(v.y + dd.y * hh.y);
            v.z = gelu_tanh(v.z + dd.z * hh.z);
            v.w = gelu_tanh(v.w + dd.w * hh.w);
        } else {
            float4 bb = *(const float4*)(bias + col);
            float4 gg = *(const float4*)(e1 + (size_t)row * DMOD + col);
            float4 sk = *(const float4*)(e2 + (size_t)row * DMOD + col);
            v.x = sk.x + gg.x * sigmoid_f(v.x + bb.x);
            v.y = sk.y + gg.y * sigmoid_f(v.y + bb.y);
            v.z = sk.z + gg.z * sigmoid_f(v.z + bb.z);
            v.w = sk.w + gg.w * sigmoid_f(v.w + bb.w);
        }
        size_t gi = (size_t)row * N + col;
        if (outF) *(float4*)(outF + gi) = v;
        if (outH) {
            uint2 uh, ul;
            split_pair(v.x, v.y, uh.x, ul.x);
            split_pair(v.z, v.w, uh.y, ul.y);
            *(uint2*)(outH + gi) = uh;
            *(uint2*)(outL + gi) = ul;
        }
    }
}

// ---------------- LayerNorm (+ bf16 hi/lo) ----------------
__global__ __launch_bounds__(128)
void ln_kernel(const float* __restrict__ h, const float* __restrict__ g,
               const float* __restrict__ b, float* __restrict__ out,
               __nv_bfloat16* __restrict__ oh, __nv_bfloat16* __restrict__ ol)
{
    const int row = blockIdx.x, t = threadIdx.x;
    float4 v = ((const float4*)(h + (size_t)row * DMOD))[t];
    float s  = v.x + v.y + v.z + v.w;
    float sq = v.x*v.x + v.y*v.y + v.z*v.z + v.w*v.w;
#pragma unroll
    for (int o = 16; o > 0; o >>= 1) {
        s  += __shfl_down_sync(0xffffffff, s,  o);
        sq += __shfl_down_sync(0xffffffff, sq, o);
    }
    __shared__ float ss[4], ssq[4];
    const int w = t >> 5, l = t & 31;
    if (l == 0) { ss[w] = s; ssq[w] = sq; }
    __syncthreads();
    if (t == 0) {
        float S = ss[0]+ss[1]+ss[2]+ss[3], SQ = ssq[0]+ssq[1]+ssq[2]+ssq[3];
        float mu = S * (1.f/DMOD);
        ss[0] = mu;
        ssq[0] = rsqrtf(SQ * (1.f/DMOD) - mu*mu + 1e-5f);
    }
    __syncthreads();
    const float mu = ss[0], rstd = ssq[0];
    float4 gv = ((const float4*)g)[t], bv = ((const float4*)b)[t];
    float4 o4;
    o4.x = (v.x-mu)*rstd*gv.x + bv.x;
    o4.y = (v.y-mu)*rstd*gv.y + bv.y;
    o4.z = (v.z-mu)*rstd*gv.z + bv.z;
    o4.w = (v.w-mu)*rstd*gv.w + bv.w;
    size_t gi = (size_t)row * DMOD + t * 4;
    *(float4*)(out + gi) = o4;
    uint2 uh, ul;
    split_pair(o4.x, o4.y, uh.x, ul.x);
    split_pair(o4.z, o4.w, uh.y, ul.y);
    *(uint2*)(oh + gi) = uh;
    *(uint2*)(ol + gi) = ul;
}

// ---------------- chunked LinOSS-IM scan ----------------
__device__ __forceinline__ void scan_params(int n, const float* __restrict__ A_diag,
                                            const float* __restrict__ ls,
                                            float& m11, float& m12, float& m21, float& m22,
                                            float& c1, float& c2)
{
    float Ad = fmaxf(A_diag[n], 0.f);
    float dt = 1.f / (1.f + expf(-ls[n]));
    float S  = 1.f / (1.f + dt*dt*Ad);
    m11 = 1.f - dt*dt*Ad*S; m12 = -dt*Ad*S; m21 = dt*S; m22 = S;
    c1 = m11*dt; c2 = m21*dt;
}

__global__ __launch_bounds__(256)
void scanA(const float* __restrict__ bre, const float* __restrict__ bim,
           const float* __restrict__ A_diag, const float* __restrict__ ls,
           float* __restrict__ st)
{
    const int n  = ((blockIdx.x & 1) << 8) + threadIdx.x;
    const int bg = blockIdx.x >> 1;
    const int g  = bg & (GCH - 1), b = bg >> 4;
    float m11, m12, m21, m22, c1, c2;
    scan_params(n, A_diag, ls, m11, m12, m21, m22, c1, c2);
    float zr = 0.f, zi = 0.f, xr = 0.f, xi = 0.f;
    size_t idx = ((size_t)b * LSEQ + (size_t)g * CLEN) * DMOD + n;
    for (int t = 0; t < CLEN; t++, idx += DMOD) {
        float br_ = bre[idx], bi_ = bim[idx];
        float nzr = fmaf(m11, zr, fmaf(m12, xr, c1 * br_));
        float nzi = fmaf(m11, zi, fmaf(m12, xi, c1 * bi_));
        float nxr = fmaf(m21, zr, fmaf(m22, xr, c2 * br_));
        float nxi = fmaf(m21, zi, fmaf(m22, xi, c2 * bi_));
        zr = nzr; zi = nzi; xr = nxr; xi = nxi;
    }
    int si = bg * DMOD + n;
    st[si] = zr; st[ST_PLANE + si] = xr;
    st[2*ST_PLANE + si] = zi; st[3*ST_PLANE + si] = xi;
}

__global__ __launch_bounds__(256)
void scanB(const float* __restrict__ A_diag, const float* __restrict__ ls,
           const float* __restrict__ st, float* __restrict__ init)
{
    const int tid = blockIdx.x * 256 + threadIdx.x;   // 0..4095
    const int n = tid & (DMOD - 1), b = tid >> 9;
    float m11, m12, m21, m22, c1, c2;
    scan_params(n, A_diag, ls, m11, m12, m21, m22, c1, c2);
    float a11 = m11, a12 = m12, a21 = m21, a22 = m22;
#pragma unroll
    for (int i = 0; i < 7; i++) {                     // T^128
        float n11 = a11*a11 + a12*a21, n12 = a11*a12 + a12*a22;
        float n21 = a21*a11 + a22*a21, n22 = a21*a12 + a22*a22;
        a11 = n11; a12 = n12; a21 = n21; a22 = n22;
    }
    float pzr = 0.f, pxr = 0.f, pzi = 0.f, pxi = 0.f;
    for (int g = 0; g < GCH; g++) {
        int si = (b * GCH + g) * DMOD + n;
        init[si] = pzr; init[ST_PLANE + si] = pxr;
        init[2*ST_PLANE + si] = pzi; init[3*ST_PLANE + si] = pxi;
        float szr = st[si], sxr = st[ST_PLANE + si];
        float szi = st[2*ST_PLANE + si], sxi = st[3*ST_PLANE + si];
        float nzr = a11*pzr + a12*pxr + szr, nxr = a21*pzr + a22*pxr + sxr;
        float nzi = a11*pzi + a12*pxi + szi, nxi = a21*pzi + a22*pxi + sxi;
        pzr = nzr; pxr = nxr; pzi = nzi; pxi = nxi;
    }
}

__global__ __launch_bounds__(256)
void scanC(const float* __restrict__ bre, const float* __restrict__ bim,
           const float* __restrict__ A_diag, const float* __restrict__ ls,
           const float* __restrict__ init,
           __nv_bfloat16* __restrict__ xrh, __nv_bfloat16* __restrict__ xrl,
           __nv_bfloat16* __restrict__ xih, __nv_bfloat16* __restrict__ xil)
{
    const int n  = ((blockIdx.x & 1) << 8) + threadIdx.x;
    const int bg = blockIdx.x >> 1;
    const int g  = bg & (GCH - 1), b = bg >> 4;
    float m11, m12, m21, m22, c1, c2;
    scan_params(n, A_diag, ls, m11, m12, m21, m22, c1, c2);
    int si = bg * DMOD + n;
    float zr = init[si], xr = init[ST_PLANE + si];
    float zi = init[2*ST_PLANE + si], xi = init[3*ST_PLANE + si];
    size_t idx = ((size_t)b * LSEQ + (size_t)g * CLEN) * DMOD + n;
    for (int t = 0; t < CLEN; t++, idx += DMOD) {
        float br_ = bre[idx], bi_ = bim[idx];
        float nzr = fmaf(m11, zr, fmaf(m12, xr, c1 * br_));
        float nzi = fmaf(m11, zi, fmaf(m12, xi, c1 * bi_));
        float nxr = fmaf(m21, zr, fmaf(m22, xr, c2 * br_));
        float nxi = fmaf(m21, zi, fmaf(m22, xi, c2 * bi_));
        zr = nzr; zi = nzi; xr = nxr; xi = nxi;
        __nv_bfloat16 hr = __float2bfloat16(xr);
        __nv_bfloat16 hi = __float2bfloat16(xi);
        xrh[idx] = hr; xrl[idx] = __float2bfloat16(xr - __bfloat162float(hr));
        xih[idx] = hi; xil[idx] = __float2bfloat16(xi - __bfloat162float(hi));
    }
}

// ---------------------------------------------------------------------------
extern "C" void kernel_launch(void* const* d_in, const int* in_sizes, int n_in,
                              void* d_out, int out_size)
{
    const float* x      = (const float*)d_in[0];
    const float* W_in   = (const float*)d_in[1];
    const float* b_in   = (const float*)d_in[2];
    const float* W_enc  = (const float*)d_in[3];
    const float* b_enc  = (const float*)d_in[4];
    const float* ln_g   = (const float*)d_in[5];
    const float* ln_b   = (const float*)d_in[6];
    const float* A_diag = (const float*)d_in[7];
    const float* lstep  = (const float*)d_in[8];
    const float* B_re   = (const float*)d_in[9];
    const float* B_im   = (const float*)d_in[10];
    const float* C_re   = (const float*)d_in[11];
    const float* C_im   = (const float*)d_in[12];
    const float* Dv     = (const float*)d_in[13];
    const float* gw1    = (const float*)d_in[14];
    const float* gb1    = (const float*)d_in[15];
    const float* gw2    = (const float*)d_in[16];
    const float* gb2    = (const float*)d_in[17];
    const float* W_dec  = (const float*)d_in[18];
    const float* b_dec  = (const float*)d_in[19];
    const float* W_out  = (const float*)d_in[20];
    const float* b_out  = (const float*)d_in[21];
    float* out = (float*)d_out;

    #define SYM(T, v, s) T* v; cudaGetSymbolAddress((void**)&v, s)
    SYM(float, H, g_H); SYM(float, HN, g_HN); SYM(float, BRE, g_BRE);
    SYM(float, BIM, g_BIM); SYM(float, G1, g_G1); SYM(float, ST, g_ST);
    SYM(float, IN, g_IN);
    SYM(__nv_bfloat16, XH, g_XH);  SYM(__nv_bfloat16, XL, g_XL);
    SYM(__nv_bfloat16, T1H, g_T1H); SYM(__nv_bfloat16, T1L, g_T1L);
    SYM(__nv_bfloat16, HNH, g_HNH); SYM(__nv_bfloat16, HNL, g_HNL);
    SYM(__nv_bfloat16, XRH, g_XRH); SYM(__nv_bfloat16, XRL, g_XRL);
    SYM(__nv_bfloat16, XIH, g_XIH); SYM(__nv_bfloat16, XIL, g_XIL);
    SYM(__nv_bfloat16, YH, g_YH);   SYM(__nv_bfloat16, YL, g_YL);
    SYM(__nv_bfloat16, H2H, g_H2H); SYM(__nv_bfloat16, H2L, g_H2L);
    SYM(__nv_bfloat16, DH, g_DH);   SYM(__nv_bfloat16, DL, g_DL);
    SYM(__nv_bfloat16, INH, w_INH);  SYM(__nv_bfloat16, INL, w_INL);
    SYM(__nv_bfloat16, ENH, w_ENCH); SYM(__nv_bfloat16, ENL, w_ENCL);
    SYM(__nv_bfloat16, BRH, w_BRH);  SYM(__nv_bfloat16, BRL, w_BRL);
    SYM(__nv_bfloat16, BIH, w_BIH);  SYM(__nv_bfloat16, BIL, w_BIL);
    SYM(__nv_bfloat16, CRH, w_CRH);  SYM(__nv_bfloat16, CRL, w_CRL);
    SYM(__nv_bfloat16, CIH, w_CIH);  SYM(__nv_bfloat16, CIL, w_CIL);
    SYM(__nv_bfloat16, G1H, w_G1H);  SYM(__nv_bfloat16, G1L, w_G1L);
    SYM(__nv_bfloat16, G2H, w_G2H);  SYM(__nv_bfloat16, G2L, w_G2L);
    SYM(__nv_bfloat16, DEH, w_DEH);  SYM(__nv_bfloat16, DEL, w_DEL);
    SYM(__nv_bfloat16, OUH, w_OUH);  SYM(__nv_bfloat16, OUL, w_OUL);
    #undef SYM

    cudaFuncSetAttribute(mma_gemm<0>, cudaFuncAttributeMaxDynamicSharedMemorySize, GEMM_SMEM);
    cudaFuncSetAttribute(mma_gemm<1>, cudaFuncAttributeMaxDynamicSharedMemorySize, GEMM_SMEM);
    cudaFuncSetAttribute(mma_gemm<2>, cudaFuncAttributeMaxDynamicSharedMemorySize, GEMM_SMEM);

    // ---- weight + input splits ----
    const int nW = DMOD * DMOD / 4, nIn = DMOD * HIN / 4;
    conv_split<<<(nIn+255)/256, 256>>>(W_in,  INH, INL, nIn, 1.f);
    conv_split<<<(nW +255)/256, 256>>>(W_enc, ENH, ENL, nW, 1.f);
    conv_split<<<(nW +255)/256, 256>>>(B_re,  BRH, BRL, nW, 1.f);
    conv_split<<<(nW +255)/256, 256>>>(B_im,  BIH, BIL, nW, 1.f);
    conv_split<<<(nW +255)/256, 256>>>(C_re,  CRH, CRL, nW, 1.f);
    conv_split<<<(nW +255)/256, 256>>>(C_im,  CIH, CIL, nW, -1.f);  // pre-negated
    conv_split<<<(nW +255)/256, 256>>>(gw1,   G1H, G1L, nW, 1.f);
    conv_split<<<(nW +255)/256, 256>>>(gw2,   G2H, G2L, nW, 1.f);
    conv_split<<<(nW +255)/256, 256>>>(W_dec, DEH, DEL, nW, 1.f);
    conv_split<<<(nIn+255)/256, 256>>>(W_out, OUH, OUL, nIn, 1.f);
    conv_split<<<(T_TOK*HIN/4+255)/256, 256>>>(x, XH, XL, T_TOK*HIN/4, 1.f);

    dim3 blk(256);
    dim3 g512(DMOD / 128, T_TOK / 128);
    dim3 g128(HIN  / 128, T_TOK / 128);

    // 1) in_proj (K=128) -> bf16 T1
    mma_gemm<0><<<g512, blk, GEMM_SMEM>>>(XH, XL, INH, INL, 0,0,0,0, b_in, 0,0,
                                          nullptr, T1H, T1L, DMOD, HIN);
    // 2) encoder -> fp32 H (skip)
    mma_gemm<0><<<g512, blk, GEMM_SMEM>>>(T1H, T1L, ENH, ENL, 0,0,0,0, b_enc, 0,0,
                                          H, nullptr, nullptr, DMOD, DMOD);
    // 3) layernorm -> HN fp32 + bf16
    ln_kernel<<<T_TOK, 128>>>(H, ln_g, ln_b, HN, HNH, HNL);
    // 4) Bu projections -> fp32
    mma_gemm<0><<<g512, blk, GEMM_SMEM>>>(HNH, HNL, BRH, BRL, 0,0,0,0, nullptr, 0,0,
                                          BRE, nullptr, nullptr, DMOD, DMOD);
    mma_gemm<0><<<g512, blk, GEMM_SMEM>>>(HNH, HNL, BIH, BIL, 0,0,0,0, nullptr, 0,0,
                                          BIM, nullptr, nullptr, DMOD, DMOD);
    // 5) chunked scan -> bf16 xs
    scanA<<<256, 256>>>(BRE, BIM, A_diag, lstep, ST);
    scanB<<<16, 256>>>(A_diag, lstep, ST, IN);
    scanC<<<256, 256>>>(BRE, BIM, A_diag, lstep, IN, XRH, XRL, XIH, XIL);
    // 6) y = gelu(xr@Cre^T + xi@(-Cim)^T + D*hn) -> bf16 Y
    mma_gemm<1><<<g512, blk, GEMM_SMEM>>>(XRH, XRL, CRH, CRL, XIH, XIL, CIH, CIL,
                                          nullptr, Dv, HN, nullptr, YH, YL, DMOD, DMOD);
    // 7) glu1 -> fp32 G1
    mma_gemm<0><<<g512, blk, GEMM_SMEM>>>(YH, YL, G1H, G1L, 0,0,0,0, gb1, 0,0,
                                          G1, nullptr, nullptr, DMOD, DMOD);
    // 8) h2 = skip + G1*sigmoid(y@gw2^T + gb2) -> bf16 H2
    mma_gemm<2><<<g512, blk, GEMM_SMEM>>>(YH, YL, G2H, G2L, 0,0,0,0, gb2, G1, H,
                                          nullptr, H2H, H2L, DMOD, DMOD);
    // 9) decoder -> bf16 D
    mma_gemm<0><<<g512, blk, GEMM_SMEM>>>(H2H, H2L, DEH, DEL, 0,0,0,0, b_dec, 0,0,
                                          nullptr, DH, DL, DMOD, DMOD);
    // 10) out_proj (N=128) -> fp32 out
    mma_gemm<0><<<g128, blk, GEMM_SMEM>>>(DH, DL, OUH, OUL, 0,0,0,0, b_out, 0,0,
                                          out, nullptr, nullptr, HIN, DMOD);
}

// round 11
// speedup vs baseline: 3.4414x; 1.0418x over previous
#include <cuda_runtime.h>
#include <cuda_bf16.h>
#include <math.h>
#include <stdint.h>

#define T_TOK 16384
#define DMOD  512
#define LSEQ  2048
#define BATCH 8
#define HIN   128
#define GCH   16
#define CLEN  128          // LSEQ / GCH
#define ST_PLANE (BATCH*GCH*DMOD)

// ---------------- scratch (__device__ globals; no cudaMalloc) ----------------
__device__ float g_H  [(size_t)T_TOK*DMOD];   // encoder out == skip (fp32)
__device__ float g_HN [(size_t)T_TOK*DMOD];   // layernorm out (fp32)
__device__ float g_BRE[(size_t)T_TOK*DMOD];   // Bu real (fp32)
__device__ float g_BIM[(size_t)T_TOK*DMOD];   // Bu imag (fp32)
__device__ float g_G1 [(size_t)T_TOK*DMOD];   // glu1 out (fp32)
__device__ float g_ST [4*ST_PLANE];           // scan chunk states
__device__ float g_IN [4*ST_PLANE];           // scan chunk init states

// bf16 hi/lo activation pairs
__device__ __nv_bfloat16 g_XH [(size_t)T_TOK*HIN],  g_XL [(size_t)T_TOK*HIN];
__device__ __nv_bfloat16 g_T1H[(size_t)T_TOK*DMOD], g_T1L[(size_t)T_TOK*DMOD];
__device__ __nv_bfloat16 g_HNH[(size_t)T_TOK*DMOD], g_HNL[(size_t)T_TOK*DMOD];
__device__ __nv_bfloat16 g_XRH[(size_t)T_TOK*DMOD], g_XRL[(size_t)T_TOK*DMOD];
__device__ __nv_bfloat16 g_XIH[(size_t)T_TOK*DMOD], g_XIL[(size_t)T_TOK*DMOD];
__device__ __nv_bfloat16 g_YH [(size_t)T_TOK*DMOD], g_YL [(size_t)T_TOK*DMOD];
__device__ __nv_bfloat16 g_H2H[(size_t)T_TOK*DMOD], g_H2L[(size_t)T_TOK*DMOD];
__device__ __nv_bfloat16 g_DH [(size_t)T_TOK*DMOD], g_DL [(size_t)T_TOK*DMOD];

// bf16 hi/lo weight pairs
__device__ __nv_bfloat16 w_INH [DMOD*HIN],  w_INL [DMOD*HIN];
__device__ __nv_bfloat16 w_ENCH[DMOD*DMOD], w_ENCL[DMOD*DMOD];
__device__ __nv_bfloat16 w_BRH [DMOD*DMOD], w_BRL [DMOD*DMOD];
__device__ __nv_bfloat16 w_BIH [DMOD*DMOD], w_BIL [DMOD*DMOD];
__device__ __nv_bfloat16 w_CRH [DMOD*DMOD], w_CRL [DMOD*DMOD];
__device__ __nv_bfloat16 w_CIH [DMOD*DMOD], w_CIL [DMOD*DMOD]; // pre-negated
__device__ __nv_bfloat16 w_G1H [DMOD*DMOD], w_G1L [DMOD*DMOD];
__device__ __nv_bfloat16 w_G2H [DMOD*DMOD], w_G2L [DMOD*DMOD];
__device__ __nv_bfloat16 w_DEH [DMOD*DMOD], w_DEL [DMOD*DMOD];
__device__ __nv_bfloat16 w_OUH [HIN*DMOD],  w_OUL [HIN*DMOD];

// ---------------- helpers ----------------
__device__ __forceinline__ float gelu_tanh(float x) {
    float x3 = x * x * x;
    return 0.5f * x * (1.f + tanhf(0.7978845608028654f * (x + 0.044715f * x3)));
}
__device__ __forceinline__ float sigmoid_f(float x) { return 1.f / (1.f + expf(-x)); }

__device__ __forceinline__ void split_pair(float a, float b, uint32_t& h, uint32_t& l) {
    __nv_bfloat16 ha = __float2bfloat16(a), hb = __float2bfloat16(b);
    __nv_bfloat162 th; th.x = ha; th.y = hb;
    __nv_bfloat162 tl;
    tl.x = __float2bfloat16(a - __bfloat162float(ha));
    tl.y = __float2bfloat16(b - __bfloat162float(hb));
    h = *reinterpret_cast<uint32_t*>(&th);
    l = *reinterpret_cast<uint32_t*>(&tl);
}
__device__ __forceinline__ uint32_t smem_u32(const void* p) {
    uint32_t a;
    asm("{ .reg .u64 t; cvta.to.shared.u64 t, %1; cvt.u32.u64 %0, t; }" : "=r"(a) : "l"(p));
    return a;
}
__device__ __forceinline__ void cp16(uint32_t smem, const void* g) {
    asm volatile("cp.async.cg.shared.global [%0], [%1], 16;" :: "r"(smem), "l"(g));
}

// ldmatrix: 4x 8x8 b16 matrices
#define LDSM4(r, addr)                                                          \
    asm volatile("ldmatrix.sync.aligned.m8n8.x4.shared.b16 {%0,%1,%2,%3}, [%4];"\
        : "=r"((r)[0]), "=r"((r)[1]), "=r"((r)[2]), "=r"((r)[3]) : "r"(addr))

// mma m16n8k16 bf16 -> fp32 accumulate in place
#define MMA16816(d, a, b)                                                       \
    asm volatile("mma.sync.aligned.m16n8k16.row.col.f32.bf16.bf16.f32 "        \
        "{%0,%1,%2,%3}, {%4,%5,%6,%7}, {%8,%9}, {%0,%1,%2,%3};"                \
        : "+f"((d)[0]), "+f"((d)[1]), "+f"((d)[2]), "+f"((d)[3])               \
        : "r"((a)[0]), "r"((a)[1]), "r"((a)[2]), "r"((a)[3]),                  \
          "r"((b)[0]), "r"((b)[1]))

// ---------------- batched fp32 -> (hi, lo) bf16 conversion ----------------
#define NJOBS 11
struct ConvArgs {
    const float4* src[NJOBS];
    uint2* dh[NJOBS];
    uint2* dl[NJOBS];
    float sgn[NJOBS];
    int start[NJOBS + 1];   // cumulative quad offsets
};

__global__ __launch_bounds__(256)
void conv_all(ConvArgs a)
{
    int i = blockIdx.x * 256 + threadIdx.x;
    if (i >= a.start[NJOBS]) return;
    int j = 0;
#pragma unroll
    for (int k = 1; k < NJOBS; k++) j += (i >= a.start[k]);
    int off = i - a.start[j];
    float4 v = a.src[j][off];
    float s = a.sgn[j];
    uint2 uh, ul;
    split_pair(s * v.x, s * v.y, uh.x, ul.x);
    split_pair(s * v.z, s * v.w, uh.y, ul.y);
    a.dh[j][off] = uh;
    a.dl[j][off] = ul;
}

// ---------------- split-bf16 GEMM on the tensor pipe (mma.sync) ----------------
// C[m,n] = sum_k A[m,k]*W[n,k]; A=AH+AL, W=BH+BL (bf16 splits); fp32 accum.
// 3-term: ah*bh + al*bh + ah*bl  (drops al*bl ~ 2^-16 relative).
// CTA tile 128x128, K-chunk 32, cp.async double-buffered (2 x 40KB SMEM).
// 8 warps: warp (wid&3) -> 32 rows, (wid>>2) -> 64 cols.
// EPI 0: v = acc (+bias[col])
// EPI 1: dual accumulate (A,W)+(A2,W2); v = gelu(acc + e1[col]*e2[row,col])
// EPI 2: v = e2[row,col] + e1[row,col]*sigmoid(acc + bias[col])
#define TILE_STRIDE 80
#define TILE_BYTES  10240
#define BUF_BYTES   40960
#define GEMM_SMEM   (2*BUF_BYTES)

__device__ __forceinline__ void load_chunk_cp(
    uint32_t sb, int buf, int tid, int bm, int bn, int K,
    const __nv_bfloat16* ah, const __nv_bfloat16* al,
    const __nv_bfloat16* bh, const __nv_bfloat16* bl, int k0)
{
    const int lrow = tid >> 2;
    const int lcb  = (tid & 3) * 16;      // byte offset within 64B row chunk
    const int lel  = lcb >> 1;            // element offset
    const __nv_bfloat16* srcs[4] = {ah, al, bh, bl};
    const int br4[4] = {bm, bm, bn, bn};
#pragma unroll
    for (int sub = 0; sub < 4; ++sub)
#pragma unroll
        for (int it = 0; it < 2; ++it) {
            int row = lrow + it * 64;
            uint32_t dst = sb + buf * BUF_BYTES + sub * TILE_BYTES + row * TILE_STRIDE + lcb;
            cp16(dst, srcs[sub] + (size_t)(br4[sub] + row) * K + k0 + lel);
        }
}

template<int EPI>
__global__ __launch_bounds__(256, 2)
void mma_gemm(const __nv_bfloat16* __restrict__ AH, const __nv_bfloat16* __restrict__ AL,
              const __nv_bfloat16* __restrict__ BH, const __nv_bfloat16* __restrict__ BL,
              const __nv_bfloat16* __restrict__ A2H, const __nv_bfloat16* __restrict__ A2L,
              const __nv_bfloat16* __restrict__ B2H, const __nv_bfloat16* __restrict__ B2L,
              const float* __restrict__ bias,
              const float* __restrict__ e1, const float* __restrict__ e2,
              float* __restrict__ outF,
              __nv_bfloat16* __restrict__ outH, __nv_bfloat16* __restrict__ outL,
              int N, int K)
{
    extern __shared__ char smem[];
    const uint32_t sb = smem_u32(smem);
    const int tid = threadIdx.x, wid = tid >> 5, lane = tid & 31;
    const int bm = blockIdx.y * 128, bn = blockIdx.x * 128;
    const int wm = (wid & 3) * 32, wn = (wid >> 2) * 64;

    float acc[2][8][4];
#pragma unroll
    for (int i = 0; i < 2; i++)
#pragma unroll
        for (int j = 0; j < 8; j++)
#pragma unroll
            for (int k = 0; k < 4; k++) acc[i][j][k] = 0.f;

    // ldmatrix lane address components
    const int a_row  = lane & 15;
    const int a_byte = (lane >> 4) * 16;
    const int bg     = lane >> 3;
    const int b_row  = (bg >> 1) * 8 + (lane & 7);
    const int b_byte = (bg & 1) * 16;

    const int kchunks = K / 32;
    const int nchunks = (EPI == 1 ? 2 : 1) * kchunks;

    // pointer/k0 selection for chunk c
    #define SEL(c, ah_, al_, bh_, bl_, k0_)                                     \
        if (EPI == 1 && (c) >= kchunks) {                                       \
            ah_ = A2H; al_ = A2L; bh_ = B2H; bl_ = B2L; k0_ = ((c) - kchunks) * 32; \
        } else { ah_ = AH; al_ = AL; bh_ = BH; bl_ = BL; k0_ = (c) * 32; }

    {   // prologue: prefetch chunk 0 into buffer 0
        const __nv_bfloat16 *ah, *al, *bh, *bl; int k0;
        SEL(0, ah, al, bh, bl, k0);
        load_chunk_cp(sb, 0, tid, bm, bn, K, ah, al, bh, bl, k0);
        asm volatile("cp.async.commit_group;" ::: "memory");
    }

    for (int c = 0; c < nchunks; ++c) {
        const int buf = c & 1;
        if (c + 1 < nchunks) {
            const __nv_bfloat16 *ah, *al, *bh, *bl; int k0;
            SEL(c + 1, ah, al, bh, bl, k0);
            load_chunk_cp(sb, (c + 1) & 1, tid, bm, bn, K, ah, al, bh, bl, k0);
        }
        asm volatile("cp.async.commit_group;" ::: "memory");
        asm volatile("cp.async.wait_group 1;" ::: "memory");
        __syncthreads();   // buf data visible to all warps

        const uint32_t tb = sb + buf * BUF_BYTES;
#pragma unroll
        for (int ks = 0; ks < 2; ++ks) {             // two k16 steps per chunk
            uint32_t af[2][4], bf[8][2], xf[2][4];
            // A-hi fragments
#pragma unroll
            for (int mt = 0; mt < 2; ++mt) {
                uint32_t ad = tb + (wm + mt * 16 + a_row) * TILE_STRIDE + ks * 32 + a_byte;
                LDSM4(af[mt], ad);
            }
            // B-hi fragments (each ldsm4 covers 2 n-tiles)
#pragma unroll
            for (int j = 0; j < 4; ++j) {
                uint32_t ad = tb + 2 * TILE_BYTES + (wn + j * 16 + b_row) * TILE_STRIDE + ks * 32 + b_byte;
                uint32_t r[4]; LDSM4(r, ad);
                bf[2*j][0] = r[0]; bf[2*j][1] = r[1];
                bf[2*j+1][0] = r[2]; bf[2*j+1][1] = r[3];
            }
#pragma unroll
            for (int mt = 0; mt < 2; ++mt)
#pragma unroll
                for (int nt = 0; nt < 8; ++nt) MMA16816(acc[mt][nt], af[mt], bf[nt]);
            // A-lo: al*bh
#pragma unroll
            for (int mt = 0; mt < 2; ++mt) {
                uint32_t ad = tb + TILE_BYTES + (wm + mt * 16 + a_row) * TILE_STRIDE + ks * 32 + a_byte;
                LDSM4(xf[mt], ad);
            }
#pragma unroll
            for (int mt = 0; mt < 2; ++mt)
#pragma unroll
                for (int nt = 0; nt < 8; ++nt) MMA16816(acc[mt][nt], xf[mt], bf[nt]);
            // B-lo (overwrite bf): ah*bl
#pragma unroll
            for (int j = 0; j < 4; ++j) {
                uint32_t ad = tb + 3 * TILE_BYTES + (wn + j * 16 + b_row) * TILE_STRIDE + ks * 32 + b_byte;
                uint32_t r[4]; LDSM4(r, ad);
                bf[2*j][0] = r[0]; bf[2*j][1] = r[1];
                bf[2*j+1][0] = r[2]; bf[2*j+1][1] = r[3];
            }
#pragma unroll
            for (int mt = 0; mt < 2; ++mt)
#pragma unroll
                for (int nt = 0; nt < 8; ++nt) MMA16816(acc[mt][nt], af[mt], bf[nt]);
        }
        __syncthreads();   // compute done before buffer is overwritten
    }
    #undef SEL

    // ---- stage accumulators to SMEM (128 x 132 fp32), then fused epilogue ----
    float* stg = (float*)smem;
#pragma unroll
    for (int mt = 0; mt < 2; ++mt)
#pragma unroll
        for (int nt = 0; nt < 8; ++nt)
#pragma unroll
            for (int h = 0; h < 2; ++h) {
                int r  = wm + mt * 16 + (lane >> 2) + h * 8;
                int cc = wn + nt * 8 + (lane & 3) * 2;
                *(float2*)(stg + r * 132 + cc) =
                    make_float2(acc[mt][nt][h * 2], acc[mt][nt][h * 2 + 1]);
            }
    __syncthreads();

    for (int i = tid; i < 128 * 32; i += 256) {
        int r = i >> 5, c4 = (i & 31) * 4;
        float4 v = *(const float4*)(stg + r * 132 + c4);
        const int row = bm + r, col = bn + c4;
        if (EPI == 0) {
            if (bias) {
                float4 bb = *(const float4*)(bias + col);
                v.x += bb.x; v.y += bb.y; v.z += bb.z; v.w += bb.w;
            }
        } else if (EPI == 1) {
            float4 dd = *(const float4*)(e1 + col);
            float4 hh = *(const float4*)(e2 + (size_t)row * DMOD + col);
            v.x = gelu_tanh(v.x + dd.x * hh.x);
            v.y = gelu_tanh(v.y + dd.y * hh.y);
            v.z = gelu_tanh(v.z + dd.z * hh.z);
            v.w = gelu_tanh(v.w + dd.w * hh.w);
        } else {
            float4 bb = *(const float4*)(bias + col);
            float4 gg = *(const float4*)(e1 + (size_t)row * DMOD + col);
            float4 sk = *(const float4*)(e2 + (size_t)row * DMOD + col);
            v.x = sk.x + gg.x * sigmoid_f(v.x + bb.x);
            v.y = sk.y + gg.y * sigmoid_f(v.y + bb.y);
            v.z = sk.z + gg.z * sigmoid_f(v.z + bb.z);
            v.w = sk.w + gg.w * sigmoid_f(v.w + bb.w);
        }
        size_t gi = (size_t)row * N + col;
        if (outF) *(float4*)(outF + gi) = v;
        if (outH) {
            uint2 uh, ul;
            split_pair(v.x, v.y, uh.x, ul.x);
            split_pair(v.z, v.w, uh.y, ul.y);
            *(uint2*)(outH + gi) = uh;
            *(uint2*)(outL + gi) = ul;
        }
    }
}

// ---------------- LayerNorm (+ bf16 hi/lo) ----------------
__global__ __launch_bounds__(128)
void ln_kernel(const float* __restrict__ h, const float* __restrict__ g,
               const float* __restrict__ b, float* __restrict__ out,
               __nv_bfloat16* __restrict__ oh, __nv_bfloat16* __restrict__ ol)
{
    const int row = blockIdx.x, t = threadIdx.x;
    float4 v = ((const float4*)(h + (size_t)row * DMOD))[t];
    float s  = v.x + v.y + v.z + v.w;
    float sq = v.x*v.x + v.y*v.y + v.z*v.z + v.w*v.w;
#pragma unroll
    for (int o = 16; o > 0; o >>= 1) {
        s  += __shfl_down_sync(0xffffffff, s,  o);
        sq += __shfl_down_sync(0xffffffff, sq, o);
    }
    __shared__ float ss[4], ssq[4];
    const int w = t >> 5, l = t & 31;
    if (l == 0) { ss[w] = s; ssq[w] = sq; }
    __syncthreads();
    if (t == 0) {
        float S = ss[0]+ss[1]+ss[2]+ss[3], SQ = ssq[0]+ssq[1]+ssq[2]+ssq[3];
        float mu = S * (1.f/DMOD);
        ss[0] = mu;
        ssq[0] = rsqrtf(SQ * (1.f/DMOD) - mu*mu + 1e-5f);
    }
    __syncthreads();
    const float mu = ss[0], rstd = ssq[0];
    float4 gv = ((const float4*)g)[t], bv = ((const float4*)b)[t];
    float4 o4;
    o4.x = (v.x-mu)*rstd*gv.x + bv.x;
    o4.y = (v.y-mu)*rstd*gv.y + bv.y;
    o4.z = (v.z-mu)*rstd*gv.z + bv.z;
    o4.w = (v.w-mu)*rstd*gv.w + bv.w;
    size_t gi = (size_t)row * DMOD + t * 4;
    *(float4*)(out + gi) = o4;
    uint2 uh, ul;
    split_pair(o4.x, o4.y, uh.x, ul.x);
    split_pair(o4.z, o4.w, uh.y, ul.y);
    *(uint2*)(oh + gi) = uh;
    *(uint2*)(ol + gi) = ul;
}

// ---------------- chunked LinOSS-IM scan ----------------
__device__ __forceinline__ void scan_params(int n, const float* __restrict__ A_diag,
                                            const float* __restrict__ ls,
                                            float& m11, float& m12, float& m21, float& m22,
                                            float& c1, float& c2)
{
    float Ad = fmaxf(A_diag[n], 0.f);
    float dt = 1.f / (1.f + expf(-ls[n]));
    float S  = 1.f / (1.f + dt*dt*Ad);
    m11 = 1.f - dt*dt*Ad*S; m12 = -dt*Ad*S; m21 = dt*S; m22 = S;
    c1 = m11*dt; c2 = m21*dt;
}

__global__ __launch_bounds__(256)
void scanA(const float* __restrict__ bre, const float* __restrict__ bim,
           const float* __restrict__ A_diag, const float* __restrict__ ls,
           float* __restrict__ st)
{
    const int n  = ((blockIdx.x & 1) << 8) + threadIdx.x;
    const int bg = blockIdx.x >> 1;
    const int g  = bg & (GCH - 1), b = bg >> 4;
    float m11, m12, m21, m22, c1, c2;
    scan_params(n, A_diag, ls, m11, m12, m21, m22, c1, c2);
    float zr = 0.f, zi = 0.f, xr = 0.f, xi = 0.f;
    size_t idx = ((size_t)b * LSEQ + (size_t)g * CLEN) * DMOD + n;
    for (int t = 0; t < CLEN; t++, idx += DMOD) {
        float br_ = bre[idx], bi_ = bim[idx];
        float nzr = fmaf(m11, zr, fmaf(m12, xr, c1 * br_));
        float nzi = fmaf(m11, zi, fmaf(m12, xi, c1 * bi_));
        float nxr = fmaf(m21, zr, fmaf(m22, xr, c2 * br_));
        float nxi = fmaf(m21, zi, fmaf(m22, xi, c2 * bi_));
        zr = nzr; zi = nzi; xr = nxr; xi = nxi;
    }
    int si = bg * DMOD + n;
    st[si] = zr; st[ST_PLANE + si] = xr;
    st[2*ST_PLANE + si] = zi; st[3*ST_PLANE + si] = xi;
}

__global__ __launch_bounds__(256)
void scanB(const float* __restrict__ A_diag, const float* __restrict__ ls,
           const float* __restrict__ st, float* __restrict__ init)
{
    const int tid = blockIdx.x * 256 + threadIdx.x;   // 0..4095
    const int n = tid & (DMOD - 1), b = tid >> 9;
    float m11, m12, m21, m22, c1, c2;
    scan_params(n, A_diag, ls, m11, m12, m21, m22, c1, c2);
    float a11 = m11, a12 = m12, a21 = m21, a22 = m22;
#pragma unroll
    for (int i = 0; i < 7; i++) {                     // T^128
        float n11 = a11*a11 + a12*a21, n12 = a11*a12 + a12*a22;
        float n21 = a21*a11 + a22*a21, n22 = a21*a12 + a22*a22;
        a11 = n11; a12 = n12; a21 = n21; a22 = n22;
    }
    float pzr = 0.f, pxr = 0.f, pzi = 0.f, pxi = 0.f;
    for (int g = 0; g < GCH; g++) {
        int si = (b * GCH + g) * DMOD + n;
        init[si] = pzr; init[ST_PLANE + si] = pxr;
        init[2*ST_PLANE + si] = pzi; init[3*ST_PLANE + si] = pxi;
        float szr = st[si], sxr = st[ST_PLANE + si];
        float szi = st[2*ST_PLANE + si], sxi = st[3*ST_PLANE + si];
        float nzr = a11*pzr + a12*pxr + szr, nxr = a21*pzr + a22*pxr + sxr;
        float nzi = a11*pzi + a12*pxi + szi, nxi = a21*pzi + a22*pxi + sxi;
        pzr = nzr; pxr = nxr; pzi = nzi; pxi = nxi;
    }
}

__global__ __launch_bounds__(256)
void scanC(const float* __restrict__ bre, const float* __restrict__ bim,
           const float* __restrict__ A_diag, const float* __restrict__ ls,
           const float* __restrict__ init,
           __nv_bfloat16* __restrict__ xrh, __nv_bfloat16* __restrict__ xrl,
           __nv_bfloat16* __restrict__ xih, __nv_bfloat16* __restrict__ xil)
{
    const int n  = ((blockIdx.x & 1) << 8) + threadIdx.x;
    const int bg = blockIdx.x >> 1;
    const int g  = bg & (GCH - 1), b = bg >> 4;
    float m11, m12, m21, m22, c1, c2;
    scan_params(n, A_diag, ls, m11, m12, m21, m22, c1, c2);
    int si = bg * DMOD + n;
    float zr = init[si], xr = init[ST_PLANE + si];
    float zi = init[2*ST_PLANE + si], xi = init[3*ST_PLANE + si];
    size_t idx = ((size_t)b * LSEQ + (size_t)g * CLEN) * DMOD + n;
    for (int t = 0; t < CLEN; t++, idx += DMOD) {
        float br_ = bre[idx], bi_ = bim[idx];
        float nzr = fmaf(m11, zr, fmaf(m12, xr, c1 * br_));
        float nzi = fmaf(m11, zi, fmaf(m12, xi, c1 * bi_));
        float nxr = fmaf(m21, zr, fmaf(m22, xr, c2 * br_));
        float nxi = fmaf(m21, zi, fmaf(m22, xi, c2 * bi_));
        zr = nzr; zi = nzi; xr = nxr; xi = nxi;
        __nv_bfloat16 hr = __float2bfloat16(xr);
        __nv_bfloat16 hi = __float2bfloat16(xi);
        xrh[idx] = hr; xrl[idx] = __float2bfloat16(xr - __bfloat162float(hr));
        xih[idx] = hi; xil[idx] = __float2bfloat16(xi - __bfloat162float(hi));
    }
}

// ---------------------------------------------------------------------------
extern "C" void kernel_launch(void* const* d_in, const int* in_sizes, int n_in,
                              void* d_out, int out_size)
{
    const float* x      = (const float*)d_in[0];
    const float* W_in   = (const float*)d_in[1];
    const float* b_in   = (const float*)d_in[2];
    const float* W_enc  = (const float*)d_in[3];
    const float* b_enc  = (const float*)d_in[4];
    const float* ln_g   = (const float*)d_in[5];
    const float* ln_b   = (const float*)d_in[6];
    const float* A_diag = (const float*)d_in[7];
    const float* lstep  = (const float*)d_in[8];
    const float* B_re   = (const float*)d_in[9];
    const float* B_im   = (const float*)d_in[10];
    const float* C_re   = (const float*)d_in[11];
    const float* C_im   = (const float*)d_in[12];
    const float* Dv     = (const float*)d_in[13];
    const float* gw1    = (const float*)d_in[14];
    const float* gb1    = (const float*)d_in[15];
    const float* gw2    = (const float*)d_in[16];
    const float* gb2    = (const float*)d_in[17];
    const float* W_dec  = (const float*)d_in[18];
    const float* b_dec  = (const float*)d_in[19];
    const float* W_out  = (const float*)d_in[20];
    const float* b_out  = (const float*)d_in[21];
    float* out = (float*)d_out;

    #define SYM(T, v, s) T* v; cudaGetSymbolAddress((void**)&v, s)
    SYM(float, H, g_H); SYM(float, HN, g_HN); SYM(float, BRE, g_BRE);
    SYM(float, BIM, g_BIM); SYM(float, G1, g_G1); SYM(float, ST, g_ST);
    SYM(float, IN, g_IN);
    SYM(__nv_bfloat16, XH, g_XH);  SYM(__nv_bfloat16, XL, g_XL);
    SYM(__nv_bfloat16, T1H, g_T1H); SYM(__nv_bfloat16, T1L, g_T1L);
    SYM(__nv_bfloat16, HNH, g_HNH); SYM(__nv_bfloat16, HNL, g_HNL);
    SYM(__nv_bfloat16, XRH, g_XRH); SYM(__nv_bfloat16, XRL, g_XRL);
    SYM(__nv_bfloat16, XIH, g_XIH); SYM(__nv_bfloat16, XIL, g_XIL);
    SYM(__nv_bfloat16, YH, g_YH);   SYM(__nv_bfloat16, YL, g_YL);
    SYM(__nv_bfloat16, H2H, g_H2H); SYM(__nv_bfloat16, H2L, g_H2L);
    SYM(__nv_bfloat16, DH, g_DH);   SYM(__nv_bfloat16, DL, g_DL);
    SYM(__nv_bfloat16, INH, w_INH);  SYM(__nv_bfloat16, INL, w_INL);
    SYM(__nv_bfloat16, ENH, w_ENCH); SYM(__nv_bfloat16, ENL, w_ENCL);
    SYM(__nv_bfloat16, BRH, w_BRH);  SYM(__nv_bfloat16, BRL, w_BRL);
    SYM(__nv_bfloat16, BIH, w_BIH);  SYM(__nv_bfloat16, BIL, w_BIL);
    SYM(__nv_bfloat16, CRH, w_CRH);  SYM(__nv_bfloat16, CRL, w_CRL);
    SYM(__nv_bfloat16, CIH, w_CIH);  SYM(__nv_bfloat16, CIL, w_CIL);
    SYM(__nv_bfloat16, G1H, w_G1H);  SYM(__nv_bfloat16, G1L, w_G1L);
    SYM(__nv_bfloat16, G2H, w_G2H);  SYM(__nv_bfloat16, G2L, w_G2L);
    SYM(__nv_bfloat16, DEH, w_DEH);  SYM(__nv_bfloat16, DEL, w_DEL);
    SYM(__nv_bfloat16, OUH, w_OUH);  SYM(__nv_bfloat16, OUL, w_OUL);
    #undef SYM

    cudaFuncSetAttribute(mma_gemm<0>, cudaFuncAttributeMaxDynamicSharedMemorySize, GEMM_SMEM);
    cudaFuncSetAttribute(mma_gemm<1>, cudaFuncAttributeMaxDynamicSharedMemorySize, GEMM_SMEM);
    cudaFuncSetAttribute(mma_gemm<2>, cudaFuncAttributeMaxDynamicSharedMemorySize, GEMM_SMEM);

    // ---- single batched conversion: 10 weights + x ----
    {
        const int qW = DMOD * DMOD / 4;     // 65536
        const int qI = DMOD * HIN / 4;      // 16384
        const int qX = T_TOK * HIN / 4;     // 524288
        ConvArgs a;
        const float* srcs[NJOBS] = {W_in, W_enc, B_re, B_im, C_re, C_im, gw1, gw2, W_dec, W_out, x};
        __nv_bfloat16* dhs[NJOBS] = {INH, ENH, BRH, BIH, CRH, CIH, G1H, G2H, DEH, OUH, XH};
        __nv_bfloat16* dls[NJOBS] = {INL, ENL, BRL, BIL, CRL, CIL, G1L, G2L, DEL, OUL, XL};
        const int sizes[NJOBS] = {qI, qW, qW, qW, qW, qW, qW, qW, qW, qI, qX};
        int acc0 = 0;
        for (int j = 0; j < NJOBS; j++) {
            a.src[j] = (const float4*)srcs[j];
            a.dh[j] = (uint2*)dhs[j];
            a.dl[j] = (uint2*)dls[j];
            a.sgn[j] = (j == 5) ? -1.f : 1.f;     // C_im pre-negated
            a.start[j] = acc0;
            acc0 += sizes[j];
        }
        a.start[NJOBS] = acc0;
        conv_all<<<(acc0 + 255) / 256, 256>>>(a);
    }

    dim3 blk(256);
    dim3 g512(DMOD / 128, T_TOK / 128);
    dim3 g128(HIN  / 128, T_TOK / 128);

    // 1) in_proj (K=128) -> bf16 T1
    mma_gemm<0><<<g512, blk, GEMM_SMEM>>>(XH, XL, INH, INL, 0,0,0,0, b_in, 0,0,
                                          nullptr, T1H, T1L, DMOD, HIN);
    // 2) encoder -> fp32 H (skip)
    mma_gemm<0><<<g512, blk, GEMM_SMEM>>>(T1H, T1L, ENH, ENL, 0,0,0,0, b_enc, 0,0,
                                          H, nullptr, nullptr, DMOD, DMOD);
    // 3) layernorm -> HN fp32 + bf16
    ln_kernel<<<T_TOK, 128>>>(H, ln_g, ln_b, HN, HNH, HNL);
    // 4) Bu projections -> fp32
    mma_gemm<0><<<g512, blk, GEMM_SMEM>>>(HNH, HNL, BRH, BRL, 0,0,0,0, nullptr, 0,0,
                                          BRE, nullptr, nullptr, DMOD, DMOD);
    mma_gemm<0><<<g512, blk, GEMM_SMEM>>>(HNH, HNL, BIH, BIL, 0,0,0,0, nullptr, 0,0,
                                          BIM, nullptr, nullptr, DMOD, DMOD);
    // 5) chunked scan -> bf16 xs
    scanA<<<256, 256>>>(BRE, BIM, A_diag, lstep, ST);
    scanB<<<16, 256>>>(A_diag, lstep, ST, IN);
    scanC<<<256, 256>>>(BRE, BIM, A_diag, lstep, IN, XRH, XRL, XIH, XIL);
    // 6) y = gelu(xr@Cre^T + xi@(-Cim)^T + D*hn) -> bf16 Y
    mma_gemm<1><<<g512, blk, GEMM_SMEM>>>(XRH, XRL, CRH, CRL, XIH, XIL, CIH, CIL,
                                          nullptr, Dv, HN, nullptr, YH, YL, DMOD, DMOD);
    // 7) glu1 -> fp32 G1
    mma_gemm<0><<<g512, blk, GEMM_SMEM>>>(YH, YL, G1H, G1L, 0,0,0,0, gb1, 0,0,
                                          G1, nullptr, nullptr, DMOD, DMOD);
    // 8) h2 = skip + G1*sigmoid(y@gw2^T + gb2) -> bf16 H2
    mma_gemm<2><<<g512, blk, GEMM_SMEM>>>(YH, YL, G2H, G2L, 0,0,0,0, gb2, G1, H,
                                          nullptr, H2H, H2L, DMOD, DMOD);
    // 9) decoder -> bf16 D
    mma_gemm<0><<<g512, blk, GEMM_SMEM>>>(H2H, H2L, DEH, DEL, 0,0,0,0, b_dec, 0,0,
                                          nullptr, DH, DL, DMOD, DMOD);
    // 10) out_proj (N=128) -> fp32 out
    mma_gemm<0><<<g128, blk, GEMM_SMEM>>>(DH, DL, OUH, OUL, 0,0,0,0, b_out, 0,0,
                                          out, nullptr, nullptr, HIN, DMOD);
}

// round 12
// speedup vs baseline: 3.8511x; 1.1190x over previous
#include <cuda_runtime.h>
#include <cuda_bf16.h>
#include <math.h>
#include <stdint.h>

#define T_TOK 16384
#define DMOD  512
#define LSEQ  2048
#define BATCH 8
#define HIN   128
#define GCH   16
#define CLEN  128          // LSEQ / GCH
#define ST_PLANE (BATCH*GCH*DMOD)

// ---------------- scratch (__device__ globals; no cudaMalloc) ----------------
__device__ float g_H  [(size_t)T_TOK*DMOD];   // encoder out == skip (fp32)
__device__ float g_HN [(size_t)T_TOK*DMOD];   // layernorm out (fp32)
__device__ float g_BU [(size_t)T_TOK*2*DMOD]; // Bu interleaved (re,im) fp32
__device__ float g_ST [4*ST_PLANE];           // scan chunk states
__device__ float g_IN [4*ST_PLANE];           // scan chunk init states

// bf16 hi/lo activation pairs
__device__ __nv_bfloat16 g_XH [(size_t)T_TOK*HIN],  g_XL [(size_t)T_TOK*HIN];
__device__ __nv_bfloat16 g_T1H[(size_t)T_TOK*DMOD], g_T1L[(size_t)T_TOK*DMOD];
__device__ __nv_bfloat16 g_HNH[(size_t)T_TOK*DMOD], g_HNL[(size_t)T_TOK*DMOD];
__device__ __nv_bfloat16 g_XRH[(size_t)T_TOK*DMOD], g_XRL[(size_t)T_TOK*DMOD];
__device__ __nv_bfloat16 g_XIH[(size_t)T_TOK*DMOD], g_XIL[(size_t)T_TOK*DMOD];
__device__ __nv_bfloat16 g_YH [(size_t)T_TOK*DMOD], g_YL [(size_t)T_TOK*DMOD];
__device__ __nv_bfloat16 g_H2H[(size_t)T_TOK*DMOD], g_H2L[(size_t)T_TOK*DMOD];
__device__ __nv_bfloat16 g_DH [(size_t)T_TOK*DMOD], g_DL [(size_t)T_TOK*DMOD];

// bf16 hi/lo weight pairs
__device__ __nv_bfloat16 w_INH [DMOD*HIN],    w_INL [DMOD*HIN];
__device__ __nv_bfloat16 w_ENCH[DMOD*DMOD],   w_ENCL[DMOD*DMOD];
__device__ __nv_bfloat16 w_BUH [2*DMOD*DMOD], w_BUL [2*DMOD*DMOD]; // interleaved [B_re;B_im]
__device__ __nv_bfloat16 w_CRH [DMOD*DMOD],   w_CRL [DMOD*DMOD];
__device__ __nv_bfloat16 w_CIH [DMOD*DMOD],   w_CIL [DMOD*DMOD];   // pre-negated
__device__ __nv_bfloat16 w_GLH [2*DMOD*DMOD], w_GLL [2*DMOD*DMOD]; // interleaved [gw1;gw2]
__device__ __nv_bfloat16 w_DEH [DMOD*DMOD],   w_DEL [DMOD*DMOD];
__device__ __nv_bfloat16 w_OUH [HIN*DMOD],    w_OUL [HIN*DMOD];

// ---------------- helpers ----------------
__device__ __forceinline__ float gelu_tanh(float x) {
    float x3 = x * x * x;
    return 0.5f * x * (1.f + tanhf(0.7978845608028654f * (x + 0.044715f * x3)));
}
__device__ __forceinline__ float sigmoid_f(float x) { return 1.f / (1.f + expf(-x)); }

__device__ __forceinline__ void split_pair(float a, float b, uint32_t& h, uint32_t& l) {
    __nv_bfloat16 ha = __float2bfloat16(a), hb = __float2bfloat16(b);
    __nv_bfloat162 th; th.x = ha; th.y = hb;
    __nv_bfloat162 tl;
    tl.x = __float2bfloat16(a - __bfloat162float(ha));
    tl.y = __float2bfloat16(b - __bfloat162float(hb));
    h = *reinterpret_cast<uint32_t*>(&th);
    l = *reinterpret_cast<uint32_t*>(&tl);
}
__device__ __forceinline__ uint32_t smem_u32(const void* p) {
    uint32_t a;
    asm("{ .reg .u64 t; cvta.to.shared.u64 t, %1; cvt.u32.u64 %0, t; }" : "=r"(a) : "l"(p));
    return a;
}
__device__ __forceinline__ void cp16(uint32_t smem, const void* g) {
    asm volatile("cp.async.cg.shared.global [%0], [%1], 16;" :: "r"(smem), "l"(g));
}

#define LDSM4(r, addr)                                                          \
    asm volatile("ldmatrix.sync.aligned.m8n8.x4.shared.b16 {%0,%1,%2,%3}, [%4];"\
        : "=r"((r)[0]), "=r"((r)[1]), "=r"((r)[2]), "=r"((r)[3]) : "r"(addr))

#define MMA16816(d, a, b)                                                       \
    asm volatile("mma.sync.aligned.m16n8k16.row.col.f32.bf16.bf16.f32 "        \
        "{%0,%1,%2,%3}, {%4,%5,%6,%7}, {%8,%9}, {%0,%1,%2,%3};"                \
        : "+f"((d)[0]), "+f"((d)[1]), "+f"((d)[2]), "+f"((d)[3])               \
        : "r"((a)[0]), "r"((a)[1]), "r"((a)[2]), "r"((a)[3]),                  \
          "r"((b)[0]), "r"((b)[1]))

// ---------------- batched fp32 -> (hi, lo) bf16 conversion ----------------
// Per-job row remap for interleaved dests: dest_quad = off + (off>>7)*extra + dbase
// (identity when extra=0, dbase=0; interleave when extra=128, dbase=0 or 128 —
//  valid only for 512-col sources where a row is exactly 128 quads)
#define NJOBS 11
struct ConvArgs {
    const float4* src[NJOBS];
    uint2* dh[NJOBS];
    uint2* dl[NJOBS];
    float sgn[NJOBS];
    int extra[NJOBS];
    int dbase[NJOBS];
    int start[NJOBS + 1];   // cumulative quad offsets
};

__global__ __launch_bounds__(256)
void conv_all(ConvArgs a)
{
    int i = blockIdx.x * 256 + threadIdx.x;
    if (i >= a.start[NJOBS]) return;
    int j = 0;
#pragma unroll
    for (int k = 1; k < NJOBS; k++) j += (i >= a.start[k]);
    int off = i - a.start[j];
    float4 v = a.src[j][off];
    float s = a.sgn[j];
    int dq = off + (off >> 7) * a.extra[j] + a.dbase[j];
    uint2 uh, ul;
    split_pair(s * v.x, s * v.y, uh.x, ul.x);
    split_pair(s * v.z, s * v.w, uh.y, ul.y);
    a.dh[j][dq] = uh;
    a.dl[j][dq] = ul;
}

// ---------------- split-bf16 GEMM on the tensor pipe (mma.sync) ----------------
// C[m,n] = sum_k A[m,k]*W[n,k]; A=AH+AL, W=BH+BL (bf16 splits); fp32 accum.
// 3-term: ah*bh + al*bh + ah*bl  (drops al*bl ~ 2^-16 relative).
// CTA tile 128x128, K-chunk 32, cp.async double-buffered (2 x 40KB SMEM).
// 8 warps: warp (wid&3) -> 32 rows, (wid>>2) -> 64 cols.
// EPI 0: v = acc (+bias[col]); store fp32 (outF) and/or bf16 hi/lo (outH/outL)
// EPI 1: dual accumulate (A,W)+(A2,W2); v = gelu(acc + e1[col]*e2[row,col])
// EPI 2: GLU-pair (interleaved N): even col = acc1, odd col = acc2;
//        h2[colout] = e2[row,colout] + (acc1+bias[colout])*sigmoid(acc2+e1[colout])
//        writes bf16 hi/lo at half width (DMOD cols)
#define TILE_STRIDE 80
#define TILE_BYTES  10240
#define BUF_BYTES   40960
#define GEMM_SMEM   (2*BUF_BYTES)

__device__ __forceinline__ void load_chunk_cp(
    uint32_t sb, int buf, int tid, int bm, int bn, int K,
    const __nv_bfloat16* ah, const __nv_bfloat16* al,
    const __nv_bfloat16* bh, const __nv_bfloat16* bl, int k0)
{
    const int lrow = tid >> 2;
    const int lcb  = (tid & 3) * 16;
    const int lel  = lcb >> 1;
    const __nv_bfloat16* srcs[4] = {ah, al, bh, bl};
    const int br4[4] = {bm, bm, bn, bn};
#pragma unroll
    for (int sub = 0; sub < 4; ++sub)
#pragma unroll
        for (int it = 0; it < 2; ++it) {
            int row = lrow + it * 64;
            uint32_t dst = sb + buf * BUF_BYTES + sub * TILE_BYTES + row * TILE_STRIDE + lcb;
            cp16(dst, srcs[sub] + (size_t)(br4[sub] + row) * K + k0 + lel);
        }
}

template<int EPI>
__global__ __launch_bounds__(256, 2)
void mma_gemm(const __nv_bfloat16* __restrict__ AH, const __nv_bfloat16* __restrict__ AL,
              const __nv_bfloat16* __restrict__ BH, const __nv_bfloat16* __restrict__ BL,
              const __nv_bfloat16* __restrict__ A2H, const __nv_bfloat16* __restrict__ A2L,
              const __nv_bfloat16* __restrict__ B2H, const __nv_bfloat16* __restrict__ B2L,
              const float* __restrict__ bias,
              const float* __restrict__ e1, const float* __restrict__ e2,
              float* __restrict__ outF,
              __nv_bfloat16* __restrict__ outH, __nv_bfloat16* __restrict__ outL,
              int N, int K)
{
    extern __shared__ char smem[];
    const uint32_t sb = smem_u32(smem);
    const int tid = threadIdx.x, wid = tid >> 5, lane = tid & 31;
    const int bm = blockIdx.y * 128, bn = blockIdx.x * 128;
    const int wm = (wid & 3) * 32, wn = (wid >> 2) * 64;

    float acc[2][8][4];
#pragma unroll
    for (int i = 0; i < 2; i++)
#pragma unroll
        for (int j = 0; j < 8; j++)
#pragma unroll
            for (int k = 0; k < 4; k++) acc[i][j][k] = 0.f;

    const int a_row  = lane & 15;
    const int a_byte = (lane >> 4) * 16;
    const int bg     = lane >> 3;
    const int b_row  = (bg >> 1) * 8 + (lane & 7);
    const int b_byte = (bg & 1) * 16;

    const int kchunks = K / 32;
    const int nchunks = (EPI == 1 ? 2 : 1) * kchunks;

    #define SEL(c, ah_, al_, bh_, bl_, k0_)                                     \
        if (EPI == 1 && (c) >= kchunks) {                                       \
            ah_ = A2H; al_ = A2L; bh_ = B2H; bl_ = B2L; k0_ = ((c) - kchunks) * 32; \
        } else { ah_ = AH; al_ = AL; bh_ = BH; bl_ = BL; k0_ = (c) * 32; }

    {
        const __nv_bfloat16 *ah, *al, *bh, *bl; int k0;
        SEL(0, ah, al, bh, bl, k0);
        load_chunk_cp(sb, 0, tid, bm, bn, K, ah, al, bh, bl, k0);
        asm volatile("cp.async.commit_group;" ::: "memory");
    }

    for (int c = 0; c < nchunks; ++c) {
        const int buf = c & 1;
        if (c + 1 < nchunks) {
            const __nv_bfloat16 *ah, *al, *bh, *bl; int k0;
            SEL(c + 1, ah, al, bh, bl, k0);
            load_chunk_cp(sb, (c + 1) & 1, tid, bm, bn, K, ah, al, bh, bl, k0);
        }
        asm volatile("cp.async.commit_group;" ::: "memory");
        asm volatile("cp.async.wait_group 1;" ::: "memory");
        __syncthreads();

        const uint32_t tb = sb + buf * BUF_BYTES;
#pragma unroll
        for (int ks = 0; ks < 2; ++ks) {
            uint32_t af[2][4], bf[8][2], xf[2][4];
#pragma unroll
            for (int mt = 0; mt < 2; ++mt) {
                uint32_t ad = tb + (wm + mt * 16 + a_row) * TILE_STRIDE + ks * 32 + a_byte;
                LDSM4(af[mt], ad);
            }
#pragma unroll
            for (int j = 0; j < 4; ++j) {
                uint32_t ad = tb + 2 * TILE_BYTES + (wn + j * 16 + b_row) * TILE_STRIDE + ks * 32 + b_byte;
                uint32_t r[4]; LDSM4(r, ad);
                bf[2*j][0] = r[0]; bf[2*j][1] = r[1];
                bf[2*j+1][0] = r[2]; bf[2*j+1][1] = r[3];
            }
#pragma unroll
            for (int mt = 0; mt < 2; ++mt)
#pragma unroll
                for (int nt = 0; nt < 8; ++nt) MMA16816(acc[mt][nt], af[mt], bf[nt]);
#pragma unroll
            for (int mt = 0; mt < 2; ++mt) {
                uint32_t ad = tb + TILE_BYTES + (wm + mt * 16 + a_row) * TILE_STRIDE + ks * 32 + a_byte;
                LDSM4(xf[mt], ad);
            }
#pragma unroll
            for (int mt = 0; mt < 2; ++mt)
#pragma unroll
                for (int nt = 0; nt < 8; ++nt) MMA16816(acc[mt][nt], xf[mt], bf[nt]);
#pragma unroll
            for (int j = 0; j < 4; ++j) {
                uint32_t ad = tb + 3 * TILE_BYTES + (wn + j * 16 + b_row) * TILE_STRIDE + ks * 32 + b_byte;
                uint32_t r[4]; LDSM4(r, ad);
                bf[2*j][0] = r[0]; bf[2*j][1] = r[1];
                bf[2*j+1][0] = r[2]; bf[2*j+1][1] = r[3];
            }
#pragma unroll
            for (int mt = 0; mt < 2; ++mt)
#pragma unroll
                for (int nt = 0; nt < 8; ++nt) MMA16816(acc[mt][nt], af[mt], bf[nt]);
        }
        __syncthreads();
    }
    #undef SEL

    // ---- stage accumulators to SMEM (128 x 132 fp32), then fused epilogue ----
    float* stg = (float*)smem;
#pragma unroll
    for (int mt = 0; mt < 2; ++mt)
#pragma unroll
        for (int nt = 0; nt < 8; ++nt)
#pragma unroll
            for (int h = 0; h < 2; ++h) {
                int r  = wm + mt * 16 + (lane >> 2) + h * 8;
                int cc = wn + nt * 8 + (lane & 3) * 2;
                *(float2*)(stg + r * 132 + cc) =
                    make_float2(acc[mt][nt][h * 2], acc[mt][nt][h * 2 + 1]);
            }
    __syncthreads();

    for (int i = tid; i < 128 * 32; i += 256) {
        int r = i >> 5, c4 = (i & 31) * 4;
        float4 v = *(const float4*)(stg + r * 132 + c4);
        const int row = bm + r, col = bn + c4;
        if (EPI == 2) {
            // GLU pair: (v.x=acc1a, v.y=acc2a, v.z=acc1b, v.w=acc2b) -> 2 outputs
            const int co = col >> 1;
            float2 sk = *(const float2*)(e2 + (size_t)row * DMOD + co);
            float h2a = sk.x + (v.x + bias[co])     * sigmoid_f(v.y + e1[co]);
            float h2b = sk.y + (v.z + bias[co + 1]) * sigmoid_f(v.w + e1[co + 1]);
            uint32_t hh, ll;
            split_pair(h2a, h2b, hh, ll);
            size_t gi = (size_t)row * DMOD + co;
            *(uint32_t*)(outH + gi) = hh;
            *(uint32_t*)(outL + gi) = ll;
            continue;
        }
        if (EPI == 0) {
            if (bias) {
                float4 bb = *(const float4*)(bias + col);
                v.x += bb.x; v.y += bb.y; v.z += bb.z; v.w += bb.w;
            }
        } else if (EPI == 1) {
            float4 dd = *(const float4*)(e1 + col);
            float4 hh = *(const float4*)(e2 + (size_t)row * DMOD + col);
            v.x = gelu_tanh(v.x + dd.x * hh.x);
            v.y = gelu_tanh(v.y + dd.y * hh.y);
            v.z = gelu_tanh(v.z + dd.z * hh.z);
            v.w = gelu_tanh(v.w + dd.w * hh.w);
        }
        size_t gi = (size_t)row * N + col;
        if (outF) *(float4*)(outF + gi) = v;
        if (outH) {
            uint2 uh, ul;
            split_pair(v.x, v.y, uh.x, ul.x);
            split_pair(v.z, v.w, uh.y, ul.y);
            *(uint2*)(outH + gi) = uh;
            *(uint2*)(outL + gi) = ul;
        }
    }
}

// ---------------- LayerNorm (+ bf16 hi/lo) ----------------
__global__ __launch_bounds__(128)
void ln_kernel(const float* __restrict__ h, const float* __restrict__ g,
               const float* __restrict__ b, float* __restrict__ out,
               __nv_bfloat16* __restrict__ oh, __nv_bfloat16* __restrict__ ol)
{
    const int row = blockIdx.x, t = threadIdx.x;
    float4 v = ((const float4*)(h + (size_t)row * DMOD))[t];
    float s  = v.x + v.y + v.z + v.w;
    float sq = v.x*v.x + v.y*v.y + v.z*v.z + v.w*v.w;
#pragma unroll
    for (int o = 16; o > 0; o >>= 1) {
        s  += __shfl_down_sync(0xffffffff, s,  o);
        sq += __shfl_down_sync(0xffffffff, sq, o);
    }
    __shared__ float ss[4], ssq[4];
    const int w = t >> 5, l = t & 31;
    if (l == 0) { ss[w] = s; ssq[w] = sq; }
    __syncthreads();
    if (t == 0) {
        float S = ss[0]+ss[1]+ss[2]+ss[3], SQ = ssq[0]+ssq[1]+ssq[2]+ssq[3];
        float mu = S * (1.f/DMOD);
        ss[0] = mu;
        ssq[0] = rsqrtf(SQ * (1.f/DMOD) - mu*mu + 1e-5f);
    }
    __syncthreads();
    const float mu = ss[0], rstd = ssq[0];
    float4 gv = ((const float4*)g)[t], bv = ((const float4*)b)[t];
    float4 o4;
    o4.x = (v.x-mu)*rstd*gv.x + bv.x;
    o4.y = (v.y-mu)*rstd*gv.y + bv.y;
    o4.z = (v.z-mu)*rstd*gv.z + bv.z;
    o4.w = (v.w-mu)*rstd*gv.w + bv.w;
    size_t gi = (size_t)row * DMOD + t * 4;
    *(float4*)(out + gi) = o4;
    uint2 uh, ul;
    split_pair(o4.x, o4.y, uh.x, ul.x);
    split_pair(o4.z, o4.w, uh.y, ul.y);
    *(uint2*)(oh + gi) = uh;
    *(uint2*)(ol + gi) = ul;
}

// ---------------- chunked LinOSS-IM scan (interleaved Bu) ----------------
__device__ __forceinline__ void scan_params(int n, const float* __restrict__ A_diag,
                                            const float* __restrict__ ls,
                                            float& m11, float& m12, float& m21, float& m22,
                                            float& c1, float& c2)
{
    float Ad = fmaxf(A_diag[n], 0.f);
    float dt = 1.f / (1.f + expf(-ls[n]));
    float S  = 1.f / (1.f + dt*dt*Ad);
    m11 = 1.f - dt*dt*Ad*S; m12 = -dt*Ad*S; m21 = dt*S; m22 = S;
    c1 = m11*dt; c2 = m21*dt;
}

__global__ __launch_bounds__(256)
void scanA(const float* __restrict__ bu,
           const float* __restrict__ A_diag, const float* __restrict__ ls,
           float* __restrict__ st)
{
    const int n  = ((blockIdx.x & 1) << 8) + threadIdx.x;
    const int bg = blockIdx.x >> 1;
    const int g  = bg & (GCH - 1), b = bg >> 4;
    float m11, m12, m21, m22, c1, c2;
    scan_params(n, A_diag, ls, m11, m12, m21, m22, c1, c2);
    float zr = 0.f, zi = 0.f, xr = 0.f, xi = 0.f;
    size_t idx = ((size_t)b * LSEQ + (size_t)g * CLEN) * (2*DMOD) + 2*n;
    for (int t = 0; t < CLEN; t++, idx += 2*DMOD) {
        float2 bv = *(const float2*)(bu + idx);
        float nzr = fmaf(m11, zr, fmaf(m12, xr, c1 * bv.x));
        float nzi = fmaf(m11, zi, fmaf(m12, xi, c1 * bv.y));
        float nxr = fmaf(m21, zr, fmaf(m22, xr, c2 * bv.x));
        float nxi = fmaf(m21, zi, fmaf(m22, xi, c2 * bv.y));
        zr = nzr; zi = nzi; xr = nxr; xi = nxi;
    }
    int si = bg * DMOD + n;
    st[si] = zr; st[ST_PLANE + si] = xr;
    st[2*ST_PLANE + si] = zi; st[3*ST_PLANE + si] = xi;
}

__global__ __launch_bounds__(256)
void scanB(const float* __restrict__ A_diag, const float* __restrict__ ls,
           const float* __restrict__ st, float* __restrict__ init)
{
    const int tid = blockIdx.x * 256 + threadIdx.x;
    const int n = tid & (DMOD - 1), b = tid >> 9;
    float m11, m12, m21, m22, c1, c2;
    scan_params(n, A_diag, ls, m11, m12, m21, m22, c1, c2);
    float a11 = m11, a12 = m12, a21 = m21, a22 = m22;
#pragma unroll
    for (int i = 0; i < 7; i++) {
        float n11 = a11*a11 + a12*a21, n12 = a11*a12 + a12*a22;
        float n21 = a21*a11 + a22*a21, n22 = a21*a12 + a22*a22;
        a11 = n11; a12 = n12; a21 = n21; a22 = n22;
    }
    float pzr = 0.f, pxr = 0.f, pzi = 0.f, pxi = 0.f;
    for (int g = 0; g < GCH; g++) {
        int si = (b * GCH + g) * DMOD + n;
        init[si] = pzr; init[ST_PLANE + si] = pxr;
        init[2*ST_PLANE + si] = pzi; init[3*ST_PLANE + si] = pxi;
        float szr = st[si], sxr = st[ST_PLANE + si];
        float szi = st[2*ST_PLANE + si], sxi = st[3*ST_PLANE + si];
        float nzr = a11*pzr + a12*pxr + szr, nxr = a21*pzr + a22*pxr + sxr;
        float nzi = a11*pzi + a12*pxi + szi, nxi = a21*pzi + a22*pxi + sxi;
        pzr = nzr; pxr = nxr; pzi = nzi; pxi = nxi;
    }
}

__global__ __launch_bounds__(256)
void scanC(const float* __restrict__ bu,
           const float* __restrict__ A_diag, const float* __restrict__ ls,
           const float* __restrict__ init,
           __nv_bfloat16* __restrict__ xrh, __nv_bfloat16* __restrict__ xrl,
           __nv_bfloat16* __restrict__ xih, __nv_bfloat16* __restrict__ xil)
{
    const int n  = ((blockIdx.x & 1) << 8) + threadIdx.x;
    const int bg = blockIdx.x >> 1;
    const int g  = bg & (GCH - 1), b = bg >> 4;
    float m11, m12, m21, m22, c1, c2;
    scan_params(n, A_diag, ls, m11, m12, m21, m22, c1, c2);
    int si = bg * DMOD + n;
    float zr = init[si], xr = init[ST_PLANE + si];
    float zi = init[2*ST_PLANE + si], xi = init[3*ST_PLANE + si];
    size_t idx  = ((size_t)b * LSEQ + (size_t)g * CLEN) * (2*DMOD) + 2*n;
    size_t odx  = ((size_t)b * LSEQ + (size_t)g * CLEN) * DMOD + n;
    for (int t = 0; t < CLEN; t++, idx += 2*DMOD, odx += DMOD) {
        float2 bv = *(const float2*)(bu + idx);
        float nzr = fmaf(m11, zr, fmaf(m12, xr, c1 * bv.x));
        float nzi = fmaf(m11, zi, fmaf(m12, xi, c1 * bv.y));
        float nxr = fmaf(m21, zr, fmaf(m22, xr, c2 * bv.x));
        float nxi = fmaf(m21, zi, fmaf(m22, xi, c2 * bv.y));
        zr = nzr; zi = nzi; xr = nxr; xi = nxi;
        __nv_bfloat16 hr = __float2bfloat16(xr);
        __nv_bfloat16 hi = __float2bfloat16(xi);
        xrh[odx] = hr; xrl[odx] = __float2bfloat16(xr - __bfloat162float(hr));
        xih[odx] = hi; xil[odx] = __float2bfloat16(xi - __bfloat162float(hi));
    }
}

// ---------------------------------------------------------------------------
extern "C" void kernel_launch(void* const* d_in, const int* in_sizes, int n_in,
                              void* d_out, int out_size)
{
    const float* x      = (const float*)d_in[0];
    const float* W_in   = (const float*)d_in[1];
    const float* b_in   = (const float*)d_in[2];
    const float* W_enc  = (const float*)d_in[3];
    const float* b_enc  = (const float*)d_in[4];
    const float* ln_g   = (const float*)d_in[5];
    const float* ln_b   = (const float*)d_in[6];
    const float* A_diag = (const float*)d_in[7];
    const float* lstep  = (const float*)d_in[8];
    const float* B_re   = (const float*)d_in[9];
    const float* B_im   = (const float*)d_in[10];
    const float* C_re   = (const float*)d_in[11];
    const float* C_im   = (const float*)d_in[12];
    const float* Dv     = (const float*)d_in[13];
    const float* gw1    = (const float*)d_in[14];
    const float* gb1    = (const float*)d_in[15];
    const float* gw2    = (const float*)d_in[16];
    const float* gb2    = (const float*)d_in[17];
    const float* W_dec  = (const float*)d_in[18];
    const float* b_dec  = (const float*)d_in[19];
    const float* W_out  = (const float*)d_in[20];
    const float* b_out  = (const float*)d_in[21];
    float* out = (float*)d_out;

    #define SYM(T, v, s) T* v; cudaGetSymbolAddress((void**)&v, s)
    SYM(float, H, g_H); SYM(float, HN, g_HN); SYM(float, BU, g_BU);
    SYM(float, ST, g_ST); SYM(float, IN, g_IN);
    SYM(__nv_bfloat16, XH, g_XH);  SYM(__nv_bfloat16, XL, g_XL);
    SYM(__nv_bfloat16, T1H, g_T1H); SYM(__nv_bfloat16, T1L, g_T1L);
    SYM(__nv_bfloat16, HNH, g_HNH); SYM(__nv_bfloat16, HNL, g_HNL);
    SYM(__nv_bfloat16, XRH, g_XRH); SYM(__nv_bfloat16, XRL, g_XRL);
    SYM(__nv_bfloat16, XIH, g_XIH); SYM(__nv_bfloat16, XIL, g_XIL);
    SYM(__nv_bfloat16, YH, g_YH);   SYM(__nv_bfloat16, YL, g_YL);
    SYM(__nv_bfloat16, H2H, g_H2H); SYM(__nv_bfloat16, H2L, g_H2L);
    SYM(__nv_bfloat16, DH, g_DH);   SYM(__nv_bfloat16, DL, g_DL);
    SYM(__nv_bfloat16, INH, w_INH);  SYM(__nv_bfloat16, INL, w_INL);
    SYM(__nv_bfloat16, ENH, w_ENCH); SYM(__nv_bfloat16, ENL, w_ENCL);
    SYM(__nv_bfloat16, BUH, w_BUH);  SYM(__nv_bfloat16, BUL, w_BUL);
    SYM(__nv_bfloat16, CRH, w_CRH);  SYM(__nv_bfloat16, CRL, w_CRL);
    SYM(__nv_bfloat16, CIH, w_CIH);  SYM(__nv_bfloat16, CIL, w_CIL);
    SYM(__nv_bfloat16, GLH, w_GLH);  SYM(__nv_bfloat16, GLL, w_GLL);
    SYM(__nv_bfloat16, DEH, w_DEH);  SYM(__nv_bfloat16, DEL, w_DEL);
    SYM(__nv_bfloat16, OUH, w_OUH);  SYM(__nv_bfloat16, OUL, w_OUL);
    #undef SYM

    cudaFuncSetAttribute(mma_gemm<0>, cudaFuncAttributeMaxDynamicSharedMemorySize, GEMM_SMEM);
    cudaFuncSetAttribute(mma_gemm<1>, cudaFuncAttributeMaxDynamicSharedMemorySize, GEMM_SMEM);
    cudaFuncSetAttribute(mma_gemm<2>, cudaFuncAttributeMaxDynamicSharedMemorySize, GEMM_SMEM);

    // ---- single batched conversion: weights (with interleave remap) + x ----
    {
        const int qW = DMOD * DMOD / 4;     // 65536 quads (128 quads/row, 512 rows)
        const int qI = DMOD * HIN / 4;      // 16384
        const int qX = T_TOK * HIN / 4;     // 524288
        ConvArgs a;
        const float* srcs[NJOBS] = {W_in, W_enc, B_re, B_im, C_re, C_im, gw1, gw2, W_dec, W_out, x};
        __nv_bfloat16* dhs[NJOBS] = {INH, ENH, BUH, BUH, CRH, CIH, GLH, GLH, DEH, OUH, XH};
        __nv_bfloat16* dls[NJOBS] = {INL, ENL, BUL, BUL, CRL, CIL, GLL, GLL, DEL, OUL, XL};
        const int sizes[NJOBS]   = {qI, qW, qW, qW, qW, qW, qW, qW, qW, qI, qX};
        const int extras[NJOBS]  = {0, 0, 128, 128, 0, 0, 128, 128, 0, 0, 0};
        const int dbases[NJOBS]  = {0, 0, 0,   128, 0, 0, 0,   128, 0, 0, 0};
        int acc0 = 0;
        for (int j = 0; j < NJOBS; j++) {
            a.src[j] = (const float4*)srcs[j];
            a.dh[j] = (uint2*)dhs[j];
            a.dl[j] = (uint2*)dls[j];
            a.sgn[j] = (j == 5) ? -1.f : 1.f;     // C_im pre-negated
            a.extra[j] = extras[j];
            a.dbase[j] = dbases[j];
            a.start[j] = acc0;
            acc0 += sizes[j];
        }
        a.start[NJOBS] = acc0;
        conv_all<<<(acc0 + 255) / 256, 256>>>(a);
    }

    dim3 blk(256);
    dim3 g512(DMOD / 128, T_TOK / 128);       // 4 x 128
    dim3 g1024(2 * DMOD / 128, T_TOK / 128);  // 8 x 128 (fused N=1024)
    dim3 g128(HIN / 128, T_TOK / 128);        // 1 x 128

    // 1) in_proj (K=128) -> bf16 T1
    mma_gemm<0><<<g512, blk, GEMM_SMEM>>>(XH, XL, INH, INL, 0,0,0,0, b_in, 0,0,
                                          nullptr, T1H, T1L, DMOD, HIN);
    // 2) encoder -> fp32 H (skip)
    mma_gemm<0><<<g512, blk, GEMM_SMEM>>>(T1H, T1L, ENH, ENL, 0,0,0,0, b_enc, 0,0,
                                          H, nullptr, nullptr, DMOD, DMOD);
    // 3) layernorm -> HN fp32 + bf16
    ln_kernel<<<T_TOK, 128>>>(H, ln_g, ln_b, HN, HNH, HNL);
    // 4) fused Bu projection (interleaved re/im, N=1024) -> fp32 BU
    mma_gemm<0><<<g1024, blk, GEMM_SMEM>>>(HNH, HNL, BUH, BUL, 0,0,0,0, nullptr, 0,0,
                                           BU, nullptr, nullptr, 2*DMOD, DMOD);
    // 5) chunked scan -> bf16 xs
    scanA<<<256, 256>>>(BU, A_diag, lstep, ST);
    scanB<<<16, 256>>>(A_diag, lstep, ST, IN);
    scanC<<<256, 256>>>(BU, A_diag, lstep, IN, XRH, XRL, XIH, XIL);
    // 6) y = gelu(xr@Cre^T + xi@(-Cim)^T + D*hn) -> bf16 Y
    mma_gemm<1><<<g512, blk, GEMM_SMEM>>>(XRH, XRL, CRH, CRL, XIH, XIL, CIH, CIL,
                                          nullptr, Dv, HN, nullptr, YH, YL, DMOD, DMOD);
    // 7) fused GLU (interleaved g1/g2, N=1024) -> bf16 H2 = skip + g1*sigmoid(g2)
    mma_gemm<2><<<g1024, blk, GEMM_SMEM>>>(YH, YL, GLH, GLL, 0,0,0,0, gb1, gb2, H,
                                           nullptr, H2H, H2L, 2*DMOD, DMOD);
    // 8) decoder -> bf16 D
    mma_gemm<0><<<g512, blk, GEMM_SMEM>>>(H2H, H2L, DEH, DEL, 0,0,0,0, b_dec, 0,0,
                                          nullptr, DH, DL, DMOD, DMOD);
    // 9) out_proj (N=128) -> fp32 out
    mma_gemm<0><<<g128, blk, GEMM_SMEM>>>(DH, DL, OUH, OUL, 0,0,0,0, b_out, 0,0,
                                          out, nullptr, nullptr, HIN, DMOD);
}